// round 8
// baseline (speedup 1.0000x reference)
#include <cuda_runtime.h>
#include <math.h>

// Problem dims
#define Bc   16
#define Sc   511
#define Fc   128
#define Dc   512
#define Hc   8
#define DHc  64
#define NBc  6
#define MLPc 2048
#define Tc   512
#define BTc  (Bc*Tc)   // 8192

// ---------------- scratch (no allocations allowed) ----------------
__device__ float g_x[(size_t)BTc*Dc];        // residual stream  [B*T, D]
__device__ float g_h[(size_t)BTc*Dc];        // LN output        [B*T, D]
__device__ float g_q[(size_t)Bc*Hc*Tc*DHc];  // [B*H, T, DH]
__device__ float g_k[(size_t)Bc*Hc*Tc*DHc];
__device__ float g_v[(size_t)Bc*Hc*Tc*DHc];
__device__ float g_m1[(size_t)BTc*MLPc];     // MLP hidden [B*T, 4D]
__device__ float g_freq[Dc];                 // pos-emb denominators

// ---------------- positional-embedding frequencies (fp64, tiny) ----
__global__ void pe_freq_kernel() {
    int d  = threadIdx.x;
    int je = d & ~1;
    g_freq[d] = (float)pow(10000.0, (double)je / 512.0);
}

// ---------------- embedding: x = src@embW + embb + PE; cls row -----
__global__ __launch_bounds__(128) void embed_kernel(
        const float* __restrict__ src, const float* __restrict__ Wemb,
        const float* __restrict__ bemb, const float* __restrict__ cls) {
    int row = blockIdx.x;               // 0..8191 = b*512 + t
    int b = row >> 9, t = row & 511;
    int tid = threadIdx.x;
    float* xo = g_x + (size_t)row * Dc;
    if (t == 0) {
        #pragma unroll
        for (int kk = 0; kk < 4; kk++) {
            int d = tid + 128*kk;
            xo[d] = cls[d] + ((d & 1) ? 1.0f : 0.0f);  // cos(0)=1, sin(0)=0
        }
        return;
    }
    __shared__ float ss[128];
    ss[tid] = src[((size_t)b*Sc + (t-1))*Fc + tid];
    __syncthreads();
    #pragma unroll
    for (int kk = 0; kk < 4; kk++) {
        int d = tid + 128*kk;
        float acc = bemb[d];
        #pragma unroll 8
        for (int f = 0; f < 128; f++) acc += ss[f] * Wemb[(size_t)f*Dc + d];
        float ang = (float)t / g_freq[d];
        acc += (d & 1) ? cosf(ang) : sinf(ang);
        xo[d] = acc;
    }
}

// ---------------- LayerNorm: g_h = LN(g_x)*g + b -------------------
__global__ __launch_bounds__(128) void ln_kernel(
        const float* __restrict__ gam, const float* __restrict__ bet) {
    int row = blockIdx.x, tid = threadIdx.x;
    const float4* xin = (const float4*)(g_x + (size_t)row*Dc);
    float4 v = xin[tid];
    float s  = v.x+v.y+v.z+v.w;
    float sq = v.x*v.x + v.y*v.y + v.z*v.z + v.w*v.w;
    #pragma unroll
    for (int o = 16; o; o >>= 1) {
        s  += __shfl_xor_sync(0xffffffffu, s,  o);
        sq += __shfl_xor_sync(0xffffffffu, sq, o);
    }
    __shared__ float sm[8];
    if ((tid & 31) == 0) { sm[tid>>5] = s; sm[4 + (tid>>5)] = sq; }
    __syncthreads();
    s  = sm[0]+sm[1]+sm[2]+sm[3];
    sq = sm[4]+sm[5]+sm[6]+sm[7];
    float mean = s * (1.f/512.f);
    float var  = sq * (1.f/512.f) - mean*mean;
    float rstd = rsqrtf(var + 1e-5f);
    float4 g4 = ((const float4*)gam)[tid];
    float4 b4 = ((const float4*)bet)[tid];
    float4 o;
    o.x = (v.x-mean)*rstd*g4.x + b4.x;
    o.y = (v.y-mean)*rstd*g4.y + b4.y;
    o.z = (v.z-mean)*rstd*g4.z + b4.z;
    o.w = (v.w-mean)*rstd*g4.w + b4.w;
    ((float4*)(g_h + (size_t)row*Dc))[tid] = o;
}

// ---------------- per-head QKV projection (64x64x64 tiles) ---------
__global__ __launch_bounds__(256) void qkv_kernel(
        const float* __restrict__ Wq, const float* __restrict__ bq,
        const float* __restrict__ Wk, const float* __restrict__ bk,
        const float* __restrict__ Wv, const float* __restrict__ bv) {
    __shared__ float Hs[64*65];   // input tile, padded (lane-varying reads)
    __shared__ float Ws[64*64];   // weights, unpadded (warp-uniform reads)
    int tid = threadIdx.x;
    int bh  = blockIdx.y; int b = bh >> 3, h = bh & 7;
    int t0  = blockIdx.x * 64;
    int z   = blockIdx.z;
    const float* W    = (z==0 ? Wq : (z==1 ? Wk : Wv)) + (size_t)h*4096;
    const float* bias = (z==0 ? bq : (z==1 ? bk : bv)) + h*64;
    float*       out  = (z==0 ? g_q : (z==1 ? g_k : g_v)) + (size_t)bh*Tc*64;

    for (int it = 0; it < 16; it++) {
        int idx = tid + 256*it; int rr = idx >> 6, cc = idx & 63;
        Hs[rr*65+cc] = g_h[((size_t)b*Tc + t0 + rr)*Dc + h*64 + cc];
        Ws[idx] = W[idx];
    }
    __syncthreads();
    int r = tid & 63, quad = tid >> 6;
    float acc[16];
    #pragma unroll
    for (int j = 0; j < 16; j++) acc[j] = bias[quad*16 + j];
    for (int d = 0; d < 64; d++) {
        float hv = Hs[r*65 + d];
        #pragma unroll
        for (int j4 = 0; j4 < 16; j4 += 4) {
            float4 wv = *(const float4*)&Ws[d*64 + quad*16 + j4];
            acc[j4+0] += hv*wv.x; acc[j4+1] += hv*wv.y;
            acc[j4+2] += hv*wv.z; acc[j4+3] += hv*wv.w;
        }
    }
    __syncthreads();
    #pragma unroll
    for (int j = 0; j < 16; j++) Hs[r*65 + quad*16 + j] = acc[j];
    __syncthreads();
    for (int it = 0; it < 16; it++) {
        int idx = tid + 256*it; int rr = idx >> 6, cc = idx & 63;
        out[(size_t)(t0+rr)*64 + cc] = Hs[rr*65+cc];
    }
}

// ---------------- flash attention + residual add -------------------
// 64 queries per CTA, 32-key tiles, online softmax. All-static smem (<48KB).
__global__ __launch_bounds__(256) void attn_kernel() {
    __shared__ float Qs[64*65];   // padded: lane-varying scalar reads
    __shared__ float Ks[32*64];   // unpadded: warp-uniform float4 reads
    __shared__ float Vs[32*64];   // unpadded: warp-uniform float4 reads
    __shared__ float Ps[64*33];   // padded: lane-varying scalar reads
    __shared__ float redM[64*4];
    __shared__ float redS[64*4];
    int tid = threadIdx.x;
    int bh  = blockIdx.y; int q0 = blockIdx.x * 64;
    const float* qb = g_q + (size_t)bh*Tc*64;
    const float* kb = g_k + (size_t)bh*Tc*64;
    const float* vb = g_v + (size_t)bh*Tc*64;

    for (int it = 0; it < 16; it++) {
        int idx = tid + 256*it; int rr = idx >> 6, cc = idx & 63;
        Qs[rr*65+cc] = qb[(size_t)(q0+rr)*64 + cc];
    }
    int r = tid & 63, quad = tid >> 6;
    float m_old = -1e30f, l_old = 0.f;
    float acc[16];
    #pragma unroll
    for (int j = 0; j < 16; j++) acc[j] = 0.f;

    for (int kt = 0; kt < 16; kt++) {
        __syncthreads();                       // prev tile's Ps/Vs reads done
        int k0 = kt * 32;
        for (int it = 0; it < 8; it++) {
            int idx = tid + 256*it; int rr = idx >> 6, cc = idx & 63;
            Ks[idx] = kb[(size_t)(k0+rr)*64 + cc];
            Vs[idx] = vb[(size_t)(k0+rr)*64 + cc];
        }
        __syncthreads();
        float s[8];
        #pragma unroll
        for (int j = 0; j < 8; j++) s[j] = 0.f;
        #pragma unroll
        for (int e4 = 0; e4 < 64; e4 += 4) {
            float q0v = Qs[r*65+e4+0], q1v = Qs[r*65+e4+1];
            float q2v = Qs[r*65+e4+2], q3v = Qs[r*65+e4+3];
            #pragma unroll
            for (int j = 0; j < 8; j++) {
                float4 kv = *(const float4*)&Ks[(quad*8+j)*64 + e4];
                s[j] += q0v*kv.x + q1v*kv.y + q2v*kv.z + q3v*kv.w;
            }
        }
        float lm = -1e30f;
        #pragma unroll
        for (int j = 0; j < 8; j++) { s[j] *= 0.125f; lm = fmaxf(lm, s[j]); }
        redM[r*4+quad] = lm;
        __syncthreads();
        float m_new = fmaxf(m_old,
            fmaxf(fmaxf(redM[r*4+0], redM[r*4+1]),
                  fmaxf(redM[r*4+2], redM[r*4+3])));
        float alpha = __expf(m_old - m_new);
        float lsum = 0.f;
        #pragma unroll
        for (int j = 0; j < 8; j++) {
            float p = __expf(s[j] - m_new);
            Ps[r*33 + quad*8 + j] = p;
            lsum += p;
        }
        redS[r*4+quad] = lsum;
        #pragma unroll
        for (int j = 0; j < 16; j++) acc[j] *= alpha;
        __syncthreads();
        l_old = l_old*alpha + (redS[r*4+0]+redS[r*4+1]+redS[r*4+2]+redS[r*4+3]);
        m_old = m_new;
        #pragma unroll 4
        for (int kc = 0; kc < 32; kc++) {
            float p = Ps[r*33 + kc];
            #pragma unroll
            for (int j4 = 0; j4 < 16; j4 += 4) {
                float4 vv = *(const float4*)&Vs[kc*64 + quad*16 + j4];
                acc[j4+0] += p*vv.x; acc[j4+1] += p*vv.y;
                acc[j4+2] += p*vv.z; acc[j4+3] += p*vv.w;
            }
        }
    }
    __syncthreads();
    float inv = 1.f / l_old;
    #pragma unroll
    for (int j = 0; j < 16; j++) Qs[r*65 + quad*16 + j] = acc[j] * inv;
    __syncthreads();
    int b = bh >> 3, h = bh & 7;
    float* xb = g_x + ((size_t)(b*Tc + q0))*Dc + h*64;
    for (int it = 0; it < 16; it++) {
        int idx = tid + 256*it; int rr = idx >> 6, cc = idx & 63;
        xb[(size_t)rr*Dc + cc] += Qs[rr*65+cc];   // residual add, exclusive region
    }
}

// ---------------- 128x128x8 SGEMM, fused epilogues -----------------
__device__ __forceinline__ float geluf(float x) {
    return 0.5f * x * (1.0f + erff(x * 0.70710678118654752f));
}

// MODE 0: C = gelu(A@B + bias)          (FC1)
// MODE 1: C = C + (A@B + bias)          (FC2, residual into g_x)
template<int MODE>
__global__ __launch_bounds__(256) void sgemm_kernel(
        const float* __restrict__ A, const float* __restrict__ Bw,
        const float* __restrict__ bias, float* __restrict__ C,
        int N, int K) {
    __shared__ float As[8][132];
    __shared__ float Bs[8][132];
    int tid = threadIdx.x;
    int tx = tid & 15, ty = tid >> 4;
    int m0 = blockIdx.y * 128, n0 = blockIdx.x * 128;
    float acc[8][8];
    #pragma unroll
    for (int i = 0; i < 8; i++)
        #pragma unroll
        for (int j = 0; j < 8; j++) acc[i][j] = 0.f;

    int arow = tid >> 1, ac4 = (tid & 1) * 4;
    int brow = tid >> 5, bc4 = (tid & 31) * 4;
    const float* Ap = A  + (size_t)(m0 + arow)*K + ac4;
    const float* Bp = Bw + (size_t)brow*N + n0 + bc4;

    for (int k0 = 0; k0 < K; k0 += 8) {
        float4 av = *(const float4*)(Ap + k0);
        float4 bv = *(const float4*)(Bp + (size_t)k0*N);
        As[ac4+0][arow] = av.x; As[ac4+1][arow] = av.y;
        As[ac4+2][arow] = av.z; As[ac4+3][arow] = av.w;
        *(float4*)&Bs[brow][bc4] = bv;
        __syncthreads();
        #pragma unroll
        for (int k = 0; k < 8; k++) {
            float a[8], bb[8];
            *(float4*)(a)    = *(const float4*)&As[k][ty*4];
            *(float4*)(a+4)  = *(const float4*)&As[k][64 + ty*4];
            *(float4*)(bb)   = *(const float4*)&Bs[k][tx*4];
            *(float4*)(bb+4) = *(const float4*)&Bs[k][64 + tx*4];
            #pragma unroll
            for (int i = 0; i < 8; i++)
                #pragma unroll
                for (int j = 0; j < 8; j++)
                    acc[i][j] += a[i]*bb[j];
        }
        __syncthreads();
    }
    #pragma unroll
    for (int i = 0; i < 8; i++) {
        int m = m0 + ((i < 4) ? (ty*4 + i) : (64 + ty*4 + i - 4));
        float* crow = C + (size_t)m*N + n0;
        #pragma unroll
        for (int hb = 0; hb < 2; hb++) {
            int nb = hb*64 + tx*4;
            float4 bbv = *(const float4*)(bias + n0 + nb);
            float4 rv;
            rv.x = acc[i][hb*4+0] + bbv.x;
            rv.y = acc[i][hb*4+1] + bbv.y;
            rv.z = acc[i][hb*4+2] + bbv.z;
            rv.w = acc[i][hb*4+3] + bbv.w;
            if (MODE == 0) {
                rv.x = geluf(rv.x); rv.y = geluf(rv.y);
                rv.z = geluf(rv.z); rv.w = geluf(rv.w);
            } else {
                float4 old = *(const float4*)(crow + nb);
                rv.x += old.x; rv.y += old.y; rv.z += old.z; rv.w += old.w;
            }
            *(float4*)(crow + nb) = rv;
        }
    }
}

// ---------------- classifier head ---------------------------------
__global__ __launch_bounds__(512) void head_kernel(
        const float* __restrict__ hW, const float* __restrict__ hb,
        float* __restrict__ out) {
    int w = threadIdx.x >> 5, lane = threadIdx.x & 31;   // 16 warps = 16 batches
    const float* xr = g_x + (size_t)w * Tc * Dc;         // token t=0
    float s = 0.f;
    for (int d = lane; d < Dc; d += 32) s += xr[d] * hW[d];
    #pragma unroll
    for (int o = 16; o; o >>= 1) s += __shfl_xor_sync(0xffffffffu, s, o);
    if (lane == 0) out[w] = 1.f / (1.f + expf(-(s + hb[0])));
}

// ---------------- launcher -----------------------------------------
extern "C" void kernel_launch(void* const* d_in, const int* in_sizes, int n_in,
                              void* d_out, int out_size) {
    const float* src  = (const float*)d_in[0];
    const float* embW = (const float*)d_in[1];
    const float* embb = (const float*)d_in[2];
    const float* cls  = (const float*)d_in[3];
    const float* ln1g = (const float*)d_in[4];
    const float* ln1b = (const float*)d_in[5];
    const float* Wq   = (const float*)d_in[6];
    const float* bq   = (const float*)d_in[7];
    const float* Wk   = (const float*)d_in[8];
    const float* bk   = (const float*)d_in[9];
    const float* Wv   = (const float*)d_in[10];
    const float* bv   = (const float*)d_in[11];
    const float* ln2g = (const float*)d_in[12];
    const float* ln2b = (const float*)d_in[13];
    const float* W1   = (const float*)d_in[14];
    const float* b1   = (const float*)d_in[15];
    const float* W2   = (const float*)d_in[16];
    const float* b2   = (const float*)d_in[17];
    const float* hW   = (const float*)d_in[18];
    const float* hb   = (const float*)d_in[19];
    float* out = (float*)d_out;

    float *ph, *pm1, *px;
    cudaGetSymbolAddress((void**)&ph,  g_h);
    cudaGetSymbolAddress((void**)&pm1, g_m1);
    cudaGetSymbolAddress((void**)&px,  g_x);

    pe_freq_kernel<<<1, 512>>>();
    embed_kernel<<<BTc, 128>>>(src, embW, embb, cls);
    for (int i = 0; i < NBc; i++) {
        ln_kernel<<<BTc, 128>>>(ln1g + i*Dc, ln1b + i*Dc);
        qkv_kernel<<<dim3(Tc/64, Bc*Hc, 3), 256>>>(
            Wq + (size_t)i*Hc*DHc*DHc, bq + (size_t)i*Hc*DHc,
            Wk + (size_t)i*Hc*DHc*DHc, bk + (size_t)i*Hc*DHc,
            Wv + (size_t)i*Hc*DHc*DHc, bv + (size_t)i*Hc*DHc);
        attn_kernel<<<dim3(Tc/64, Bc*Hc), 256>>>();
        ln_kernel<<<BTc, 128>>>(ln2g + i*Dc, ln2b + i*Dc);
        sgemm_kernel<0><<<dim3(MLPc/128, BTc/128), 256>>>(
            ph, W1 + (size_t)i*Dc*MLPc, b1 + (size_t)i*MLPc, pm1, MLPc, Dc);
        sgemm_kernel<1><<<dim3(Dc/128, BTc/128), 256>>>(
            pm1, W2 + (size_t)i*MLPc*Dc, b2 + (size_t)i*Dc, px, Dc, MLPc);
    }
    head_kernel<<<1, 512>>>(hW, hb, out);
}

// round 9
// speedup vs baseline: 1.0546x; 1.0546x over previous
#include <cuda_runtime.h>
#include <math.h>

// Problem dims
#define Bc   16
#define Sc   511
#define Fc   128
#define Dc   512
#define Hc   8
#define DHc  64
#define NBc  6
#define MLPc 2048
#define Tc   512
#define BTc  (Bc*Tc)   // 8192

// ---------------- scratch (no allocations allowed) ----------------
__device__ float g_x[(size_t)BTc*Dc];        // residual stream  [B*T, D]
__device__ float g_h[(size_t)BTc*Dc];        // LN output        [B*T, D]
__device__ float g_q[(size_t)Bc*Hc*Tc*DHc];  // [B*H, T, DH]
__device__ float g_k[(size_t)Bc*Hc*Tc*DHc];
__device__ float g_v[(size_t)Bc*Hc*Tc*DHc];
__device__ float g_m1[(size_t)BTc*MLPc];     // MLP hidden [B*T, 4D]
__device__ float g_freq[Dc];                 // pos-emb denominators

// ---------------- positional-embedding frequencies (fp64, tiny) ----
__global__ void pe_freq_kernel() {
    int d  = threadIdx.x;
    int je = d & ~1;
    g_freq[d] = (float)pow(10000.0, (double)je / 512.0);
}

// ---------------- embedding: x = src@embW + embb + PE; cls row -----
__global__ __launch_bounds__(128) void embed_kernel(
        const float* __restrict__ src, const float* __restrict__ Wemb,
        const float* __restrict__ bemb, const float* __restrict__ cls) {
    int row = blockIdx.x;               // 0..8191 = b*512 + t
    int b = row >> 9, t = row & 511;
    int tid = threadIdx.x;
    float* xo = g_x + (size_t)row * Dc;
    if (t == 0) {
        #pragma unroll
        for (int kk = 0; kk < 4; kk++) {
            int d = tid + 128*kk;
            xo[d] = cls[d] + ((d & 1) ? 1.0f : 0.0f);  // cos(0)=1, sin(0)=0
        }
        return;
    }
    __shared__ float ss[128];
    ss[tid] = src[((size_t)b*Sc + (t-1))*Fc + tid];
    __syncthreads();
    #pragma unroll
    for (int kk = 0; kk < 4; kk++) {
        int d = tid + 128*kk;
        float acc = bemb[d];
        #pragma unroll 8
        for (int f = 0; f < 128; f++) acc += ss[f] * Wemb[(size_t)f*Dc + d];
        float ang = (float)t / g_freq[d];
        acc += (d & 1) ? cosf(ang) : sinf(ang);
        xo[d] = acc;
    }
}

// ---------------- LayerNorm: g_h = LN(g_x)*g + b -------------------
__global__ __launch_bounds__(128) void ln_kernel(
        const float* __restrict__ gam, const float* __restrict__ bet) {
    int row = blockIdx.x, tid = threadIdx.x;
    const float4* xin = (const float4*)(g_x + (size_t)row*Dc);
    float4 v = xin[tid];
    float s  = v.x+v.y+v.z+v.w;
    float sq = v.x*v.x + v.y*v.y + v.z*v.z + v.w*v.w;
    #pragma unroll
    for (int o = 16; o; o >>= 1) {
        s  += __shfl_xor_sync(0xffffffffu, s,  o);
        sq += __shfl_xor_sync(0xffffffffu, sq, o);
    }
    __shared__ float sm[8];
    if ((tid & 31) == 0) { sm[tid>>5] = s; sm[4 + (tid>>5)] = sq; }
    __syncthreads();
    s  = sm[0]+sm[1]+sm[2]+sm[3];
    sq = sm[4]+sm[5]+sm[6]+sm[7];
    float mean = s * (1.f/512.f);
    float var  = sq * (1.f/512.f) - mean*mean;
    float rstd = rsqrtf(var + 1e-5f);
    float4 g4 = ((const float4*)gam)[tid];
    float4 b4 = ((const float4*)bet)[tid];
    float4 o;
    o.x = (v.x-mean)*rstd*g4.x + b4.x;
    o.y = (v.y-mean)*rstd*g4.y + b4.y;
    o.z = (v.z-mean)*rstd*g4.z + b4.z;
    o.w = (v.w-mean)*rstd*g4.w + b4.w;
    ((float4*)(g_h + (size_t)row*Dc))[tid] = o;
}

// ---------------- per-head QKV projection (64x64x64 tiles) ---------
__global__ __launch_bounds__(256) void qkv_kernel(
        const float* __restrict__ Wq, const float* __restrict__ bq,
        const float* __restrict__ Wk, const float* __restrict__ bk,
        const float* __restrict__ Wv, const float* __restrict__ bv) {
    __shared__ float Hs[64*65];   // input tile, padded (lane-varying reads)
    __shared__ float Ws[64*64];   // weights, unpadded (warp-uniform reads)
    int tid = threadIdx.x;
    int bh  = blockIdx.y; int b = bh >> 3, h = bh & 7;
    int t0  = blockIdx.x * 64;
    int z   = blockIdx.z;
    const float* W    = (z==0 ? Wq : (z==1 ? Wk : Wv)) + (size_t)h*4096;
    const float* bias = (z==0 ? bq : (z==1 ? bk : bv)) + h*64;
    float*       out  = (z==0 ? g_q : (z==1 ? g_k : g_v)) + (size_t)bh*Tc*64;

    for (int it = 0; it < 16; it++) {
        int idx = tid + 256*it; int rr = idx >> 6, cc = idx & 63;
        Hs[rr*65+cc] = g_h[((size_t)b*Tc + t0 + rr)*Dc + h*64 + cc];
        Ws[idx] = W[idx];
    }
    __syncthreads();
    int r = tid & 63, quad = tid >> 6;
    float acc[16];
    #pragma unroll
    for (int j = 0; j < 16; j++) acc[j] = bias[quad*16 + j];
    for (int d = 0; d < 64; d++) {
        float hv = Hs[r*65 + d];
        #pragma unroll
        for (int j4 = 0; j4 < 16; j4 += 4) {
            float4 wv = *(const float4*)&Ws[d*64 + quad*16 + j4];
            acc[j4+0] += hv*wv.x; acc[j4+1] += hv*wv.y;
            acc[j4+2] += hv*wv.z; acc[j4+3] += hv*wv.w;
        }
    }
    __syncthreads();
    #pragma unroll
    for (int j = 0; j < 16; j++) Hs[r*65 + quad*16 + j] = acc[j];
    __syncthreads();
    for (int it = 0; it < 16; it++) {
        int idx = tid + 256*it; int rr = idx >> 6, cc = idx & 63;
        out[(size_t)(t0+rr)*64 + cc] = Hs[rr*65+cc];
    }
}

// ---------------- flash attention + residual add -------------------
// 64 queries per CTA, 32-key tiles, online softmax. All-static smem (<48KB).
__global__ __launch_bounds__(256) void attn_kernel() {
    __shared__ float Qs[64*65];   // padded: lane-varying scalar reads
    __shared__ float Ks[32*64];   // unpadded: warp-uniform float4 reads
    __shared__ float Vs[32*64];   // unpadded: warp-uniform float4 reads
    __shared__ float Ps[64*33];   // padded: lane-varying scalar reads
    __shared__ float redM[64*4];
    __shared__ float redS[64*4];
    int tid = threadIdx.x;
    int bh  = blockIdx.y; int q0 = blockIdx.x * 64;
    const float* qb = g_q + (size_t)bh*Tc*64;
    const float* kb = g_k + (size_t)bh*Tc*64;
    const float* vb = g_v + (size_t)bh*Tc*64;

    for (int it = 0; it < 16; it++) {
        int idx = tid + 256*it; int rr = idx >> 6, cc = idx & 63;
        Qs[rr*65+cc] = qb[(size_t)(q0+rr)*64 + cc];
    }
    int r = tid & 63, quad = tid >> 6;
    float m_old = -1e30f, l_old = 0.f;
    float acc[16];
    #pragma unroll
    for (int j = 0; j < 16; j++) acc[j] = 0.f;

    for (int kt = 0; kt < 16; kt++) {
        __syncthreads();                       // prev tile's Ps/Vs reads done
        int k0 = kt * 32;
        for (int it = 0; it < 8; it++) {
            int idx = tid + 256*it; int rr = idx >> 6, cc = idx & 63;
            Ks[idx] = kb[(size_t)(k0+rr)*64 + cc];
            Vs[idx] = vb[(size_t)(k0+rr)*64 + cc];
        }
        __syncthreads();
        float s[8];
        #pragma unroll
        for (int j = 0; j < 8; j++) s[j] = 0.f;
        #pragma unroll
        for (int e4 = 0; e4 < 64; e4 += 4) {
            float q0v = Qs[r*65+e4+0], q1v = Qs[r*65+e4+1];
            float q2v = Qs[r*65+e4+2], q3v = Qs[r*65+e4+3];
            #pragma unroll
            for (int j = 0; j < 8; j++) {
                float4 kv = *(const float4*)&Ks[(quad*8+j)*64 + e4];
                s[j] += q0v*kv.x + q1v*kv.y + q2v*kv.z + q3v*kv.w;
            }
        }
        float lm = -1e30f;
        #pragma unroll
        for (int j = 0; j < 8; j++) { s[j] *= 0.125f; lm = fmaxf(lm, s[j]); }
        redM[r*4+quad] = lm;
        __syncthreads();
        float m_new = fmaxf(m_old,
            fmaxf(fmaxf(redM[r*4+0], redM[r*4+1]),
                  fmaxf(redM[r*4+2], redM[r*4+3])));
        float alpha = __expf(m_old - m_new);
        float lsum = 0.f;
        #pragma unroll
        for (int j = 0; j < 8; j++) {
            float p = __expf(s[j] - m_new);
            Ps[r*33 + quad*8 + j] = p;
            lsum += p;
        }
        redS[r*4+quad] = lsum;
        #pragma unroll
        for (int j = 0; j < 16; j++) acc[j] *= alpha;
        __syncthreads();
        l_old = l_old*alpha + (redS[r*4+0]+redS[r*4+1]+redS[r*4+2]+redS[r*4+3]);
        m_old = m_new;
        #pragma unroll 4
        for (int kc = 0; kc < 32; kc++) {
            float p = Ps[r*33 + kc];
            #pragma unroll
            for (int j4 = 0; j4 < 16; j4 += 4) {
                float4 vv = *(const float4*)&Vs[kc*64 + quad*16 + j4];
                acc[j4+0] += p*vv.x; acc[j4+1] += p*vv.y;
                acc[j4+2] += p*vv.z; acc[j4+3] += p*vv.w;
            }
        }
    }
    __syncthreads();
    float inv = 1.f / l_old;
    #pragma unroll
    for (int j = 0; j < 16; j++) Qs[r*65 + quad*16 + j] = acc[j] * inv;
    __syncthreads();
    int b = bh >> 3, h = bh & 7;
    float* xb = g_x + ((size_t)(b*Tc + q0))*Dc + h*64;
    for (int it = 0; it < 16; it++) {
        int idx = tid + 256*it; int rr = idx >> 6, cc = idx & 63;
        xb[(size_t)rr*Dc + cc] += Qs[rr*65+cc];   // residual add, exclusive region
    }
}

// ---------------- 128x128x8 SGEMM, fused epilogues -----------------
__device__ __forceinline__ float geluf(float x) {
    return 0.5f * x * (1.0f + erff(x * 0.70710678118654752f));
}

// MODE 0: C = gelu(A@B + bias)          (FC1)
// MODE 1: C = C + (A@B + bias)          (FC2, residual into g_x)
template<int MODE>
__global__ __launch_bounds__(256) void sgemm_kernel(
        const float* __restrict__ A, const float* __restrict__ Bw,
        const float* __restrict__ bias, float* __restrict__ C,
        int N, int K) {
    __shared__ float As[8][132];
    __shared__ float Bs[8][132];
    int tid = threadIdx.x;
    int tx = tid & 15, ty = tid >> 4;
    int m0 = blockIdx.y * 128, n0 = blockIdx.x * 128;
    float acc[8][8];
    #pragma unroll
    for (int i = 0; i < 8; i++)
        #pragma unroll
        for (int j = 0; j < 8; j++) acc[i][j] = 0.f;

    int arow = tid >> 1, ac4 = (tid & 1) * 4;
    int brow = tid >> 5, bc4 = (tid & 31) * 4;
    const float* Ap = A  + (size_t)(m0 + arow)*K + ac4;
    const float* Bp = Bw + (size_t)brow*N + n0 + bc4;

    for (int k0 = 0; k0 < K; k0 += 8) {
        float4 av = *(const float4*)(Ap + k0);
        float4 bv = *(const float4*)(Bp + (size_t)k0*N);
        As[ac4+0][arow] = av.x; As[ac4+1][arow] = av.y;
        As[ac4+2][arow] = av.z; As[ac4+3][arow] = av.w;
        *(float4*)&Bs[brow][bc4] = bv;
        __syncthreads();
        #pragma unroll
        for (int k = 0; k < 8; k++) {
            float a[8], bb[8];
            *(float4*)(a)    = *(const float4*)&As[k][ty*4];
            *(float4*)(a+4)  = *(const float4*)&As[k][64 + ty*4];
            *(float4*)(bb)   = *(const float4*)&Bs[k][tx*4];
            *(float4*)(bb+4) = *(const float4*)&Bs[k][64 + tx*4];
            #pragma unroll
            for (int i = 0; i < 8; i++)
                #pragma unroll
                for (int j = 0; j < 8; j++)
                    acc[i][j] += a[i]*bb[j];
        }
        __syncthreads();
    }
    #pragma unroll
    for (int i = 0; i < 8; i++) {
        int m = m0 + ((i < 4) ? (ty*4 + i) : (64 + ty*4 + i - 4));
        float* crow = C + (size_t)m*N + n0;
        #pragma unroll
        for (int hb = 0; hb < 2; hb++) {
            int nb = hb*64 + tx*4;
            float4 bbv = *(const float4*)(bias + n0 + nb);
            float4 rv;
            rv.x = acc[i][hb*4+0] + bbv.x;
            rv.y = acc[i][hb*4+1] + bbv.y;
            rv.z = acc[i][hb*4+2] + bbv.z;
            rv.w = acc[i][hb*4+3] + bbv.w;
            if (MODE == 0) {
                rv.x = geluf(rv.x); rv.y = geluf(rv.y);
                rv.z = geluf(rv.z); rv.w = geluf(rv.w);
            } else {
                float4 old = *(const float4*)(crow + nb);
                rv.x += old.x; rv.y += old.y; rv.z += old.z; rv.w += old.w;
            }
            *(float4*)(crow + nb) = rv;
        }
    }
}

// ---------------- classifier head ---------------------------------
__global__ __launch_bounds__(512) void head_kernel(
        const float* __restrict__ hW, const float* __restrict__ hb,
        float* __restrict__ out) {
    int w = threadIdx.x >> 5, lane = threadIdx.x & 31;   // 16 warps = 16 batches
    const float* xr = g_x + (size_t)w * Tc * Dc;         // token t=0
    float s = 0.f;
    for (int d = lane; d < Dc; d += 32) s += xr[d] * hW[d];
    #pragma unroll
    for (int o = 16; o; o >>= 1) s += __shfl_xor_sync(0xffffffffu, s, o);
    if (lane == 0) out[w] = 1.f / (1.f + expf(-(s + hb[0])));
}

// ---------------- launcher -----------------------------------------
extern "C" void kernel_launch(void* const* d_in, const int* in_sizes, int n_in,
                              void* d_out, int out_size) {
    const float* src  = (const float*)d_in[0];
    const float* embW = (const float*)d_in[1];
    const float* embb = (const float*)d_in[2];
    const float* cls  = (const float*)d_in[3];
    const float* ln1g = (const float*)d_in[4];
    const float* ln1b = (const float*)d_in[5];
    const float* Wq   = (const float*)d_in[6];
    const float* bq   = (const float*)d_in[7];
    const float* Wk   = (const float*)d_in[8];
    const float* bk   = (const float*)d_in[9];
    const float* Wv   = (const float*)d_in[10];
    const float* bv   = (const float*)d_in[11];
    const float* ln2g = (const float*)d_in[12];
    const float* ln2b = (const float*)d_in[13];
    const float* W1   = (const float*)d_in[14];
    const float* b1   = (const float*)d_in[15];
    const float* W2   = (const float*)d_in[16];
    const float* b2   = (const float*)d_in[17];
    const float* hW   = (const float*)d_in[18];
    const float* hb   = (const float*)d_in[19];
    float* out = (float*)d_out;

    float *ph, *pm1, *px;
    cudaGetSymbolAddress((void**)&ph,  g_h);
    cudaGetSymbolAddress((void**)&pm1, g_m1);
    cudaGetSymbolAddress((void**)&px,  g_x);

    pe_freq_kernel<<<1, 512>>>();
    embed_kernel<<<BTc, 128>>>(src, embW, embb, cls);
    for (int i = 0; i < NBc; i++) {
        ln_kernel<<<BTc, 128>>>(ln1g + i*Dc, ln1b + i*Dc);
        qkv_kernel<<<dim3(Tc/64, Bc*Hc, 3), 256>>>(
            Wq + (size_t)i*Hc*DHc*DHc, bq + (size_t)i*Hc*DHc,
            Wk + (size_t)i*Hc*DHc*DHc, bk + (size_t)i*Hc*DHc,
            Wv + (size_t)i*Hc*DHc*DHc, bv + (size_t)i*Hc*DHc);
        attn_kernel<<<dim3(Tc/64, Bc*Hc), 256>>>();
        ln_kernel<<<BTc, 128>>>(ln2g + i*Dc, ln2b + i*Dc);
        sgemm_kernel<0><<<dim3(MLPc/128, BTc/128), 256>>>(
            ph, W1 + (size_t)i*Dc*MLPc, b1 + (size_t)i*MLPc, pm1, MLPc, Dc);
        sgemm_kernel<1><<<dim3(Dc/128, BTc/128), 256>>>(
            pm1, W2 + (size_t)i*MLPc*Dc, b2 + (size_t)i*Dc, px, Dc, MLPc);
    }
    head_kernel<<<1, 512>>>(hW, hb, out);
}

// round 10
// speedup vs baseline: 1.0548x; 1.0002x over previous
#include <cuda_runtime.h>
#include <math.h>

// Problem dims
#define Bc   16
#define Sc   511
#define Fc   128
#define Dc   512
#define Hc   8
#define DHc  64
#define NBc  6
#define MLPc 2048
#define Tc   512
#define BTc  (Bc*Tc)   // 8192

// ---------------- scratch (no allocations allowed) ----------------
__device__ float g_x[(size_t)BTc*Dc];        // residual stream  [B*T, D]
__device__ float g_h[(size_t)BTc*Dc];        // LN output        [B*T, D]
__device__ float g_q[(size_t)Bc*Hc*Tc*DHc];  // [B*H, T, DH]
__device__ float g_k[(size_t)Bc*Hc*Tc*DHc];
__device__ float g_v[(size_t)Bc*Hc*Tc*DHc];
__device__ float g_m1[(size_t)BTc*MLPc];     // MLP hidden [B*T, 4D]
__device__ float g_freq[Dc];                 // pos-emb denominators

// ---------------- positional-embedding frequencies (fp64, tiny) ----
__global__ void pe_freq_kernel() {
    int d  = threadIdx.x;
    int je = d & ~1;
    g_freq[d] = (float)pow(10000.0, (double)je / 512.0);
}

// ---------------- embedding: x = src@embW + embb + PE; cls row -----
__global__ __launch_bounds__(128) void embed_kernel(
        const float* __restrict__ src, const float* __restrict__ Wemb,
        const float* __restrict__ bemb, const float* __restrict__ cls) {
    int row = blockIdx.x;               // 0..8191 = b*512 + t
    int b = row >> 9, t = row & 511;
    int tid = threadIdx.x;
    float* xo = g_x + (size_t)row * Dc;
    if (t == 0) {
        #pragma unroll
        for (int kk = 0; kk < 4; kk++) {
            int d = tid + 128*kk;
            xo[d] = cls[d] + ((d & 1) ? 1.0f : 0.0f);  // cos(0)=1, sin(0)=0
        }
        return;
    }
    __shared__ float ss[128];
    ss[tid] = src[((size_t)b*Sc + (t-1))*Fc + tid];
    __syncthreads();
    #pragma unroll
    for (int kk = 0; kk < 4; kk++) {
        int d = tid + 128*kk;
        float acc = bemb[d];
        #pragma unroll 8
        for (int f = 0; f < 128; f++) acc += ss[f] * Wemb[(size_t)f*Dc + d];
        float ang = (float)t / g_freq[d];
        acc += (d & 1) ? cosf(ang) : sinf(ang);
        xo[d] = acc;
    }
}

// ---------------- LayerNorm: g_h = LN(g_x)*g + b -------------------
__global__ __launch_bounds__(128) void ln_kernel(
        const float* __restrict__ gam, const float* __restrict__ bet) {
    int row = blockIdx.x, tid = threadIdx.x;
    const float4* xin = (const float4*)(g_x + (size_t)row*Dc);
    float4 v = xin[tid];
    float s  = v.x+v.y+v.z+v.w;
    float sq = v.x*v.x + v.y*v.y + v.z*v.z + v.w*v.w;
    #pragma unroll
    for (int o = 16; o; o >>= 1) {
        s  += __shfl_xor_sync(0xffffffffu, s,  o);
        sq += __shfl_xor_sync(0xffffffffu, sq, o);
    }
    __shared__ float sm[8];
    if ((tid & 31) == 0) { sm[tid>>5] = s; sm[4 + (tid>>5)] = sq; }
    __syncthreads();
    s  = sm[0]+sm[1]+sm[2]+sm[3];
    sq = sm[4]+sm[5]+sm[6]+sm[7];
    float mean = s * (1.f/512.f);
    float var  = sq * (1.f/512.f) - mean*mean;
    float rstd = rsqrtf(var + 1e-5f);
    float4 g4 = ((const float4*)gam)[tid];
    float4 b4 = ((const float4*)bet)[tid];
    float4 o;
    o.x = (v.x-mean)*rstd*g4.x + b4.x;
    o.y = (v.y-mean)*rstd*g4.y + b4.y;
    o.z = (v.z-mean)*rstd*g4.z + b4.z;
    o.w = (v.w-mean)*rstd*g4.w + b4.w;
    ((float4*)(g_h + (size_t)row*Dc))[tid] = o;
}

// ---------------- per-head QKV projection (64x64x64 tiles) ---------
__global__ __launch_bounds__(256) void qkv_kernel(
        const float* __restrict__ Wq, const float* __restrict__ bq,
        const float* __restrict__ Wk, const float* __restrict__ bk,
        const float* __restrict__ Wv, const float* __restrict__ bv) {
    __shared__ float Hs[64*65];   // input tile, padded (lane-varying reads)
    __shared__ float Ws[64*64];   // weights, unpadded (warp-uniform reads)
    int tid = threadIdx.x;
    int bh  = blockIdx.y; int b = bh >> 3, h = bh & 7;
    int t0  = blockIdx.x * 64;
    int z   = blockIdx.z;
    const float* W    = (z==0 ? Wq : (z==1 ? Wk : Wv)) + (size_t)h*4096;
    const float* bias = (z==0 ? bq : (z==1 ? bk : bv)) + h*64;
    float*       out  = (z==0 ? g_q : (z==1 ? g_k : g_v)) + (size_t)bh*Tc*64;

    for (int it = 0; it < 16; it++) {
        int idx = tid + 256*it; int rr = idx >> 6, cc = idx & 63;
        Hs[rr*65+cc] = g_h[((size_t)b*Tc + t0 + rr)*Dc + h*64 + cc];
        Ws[idx] = W[idx];
    }
    __syncthreads();
    int r = tid & 63, quad = tid >> 6;
    float acc[16];
    #pragma unroll
    for (int j = 0; j < 16; j++) acc[j] = bias[quad*16 + j];
    for (int d = 0; d < 64; d++) {
        float hv = Hs[r*65 + d];
        #pragma unroll
        for (int j4 = 0; j4 < 16; j4 += 4) {
            float4 wv = *(const float4*)&Ws[d*64 + quad*16 + j4];
            acc[j4+0] += hv*wv.x; acc[j4+1] += hv*wv.y;
            acc[j4+2] += hv*wv.z; acc[j4+3] += hv*wv.w;
        }
    }
    __syncthreads();
    #pragma unroll
    for (int j = 0; j < 16; j++) Hs[r*65 + quad*16 + j] = acc[j];
    __syncthreads();
    for (int it = 0; it < 16; it++) {
        int idx = tid + 256*it; int rr = idx >> 6, cc = idx & 63;
        out[(size_t)(t0+rr)*64 + cc] = Hs[rr*65+cc];
    }
}

// ---------------- flash attention + residual add -------------------
// 64 queries per CTA, 32-key tiles, online softmax. All-static smem (<48KB).
__global__ __launch_bounds__(256) void attn_kernel() {
    __shared__ float Qs[64*65];   // padded: lane-varying scalar reads
    __shared__ float Ks[32*64];   // unpadded: warp-uniform float4 reads
    __shared__ float Vs[32*64];   // unpadded: warp-uniform float4 reads
    __shared__ float Ps[64*33];   // padded: lane-varying scalar reads
    __shared__ float redM[64*4];
    __shared__ float redS[64*4];
    int tid = threadIdx.x;
    int bh  = blockIdx.y; int q0 = blockIdx.x * 64;
    const float* qb = g_q + (size_t)bh*Tc*64;
    const float* kb = g_k + (size_t)bh*Tc*64;
    const float* vb = g_v + (size_t)bh*Tc*64;

    for (int it = 0; it < 16; it++) {
        int idx = tid + 256*it; int rr = idx >> 6, cc = idx & 63;
        Qs[rr*65+cc] = qb[(size_t)(q0+rr)*64 + cc];
    }
    int r = tid & 63, quad = tid >> 6;
    float m_old = -1e30f, l_old = 0.f;
    float acc[16];
    #pragma unroll
    for (int j = 0; j < 16; j++) acc[j] = 0.f;

    for (int kt = 0; kt < 16; kt++) {
        __syncthreads();                       // prev tile's Ps/Vs reads done
        int k0 = kt * 32;
        for (int it = 0; it < 8; it++) {
            int idx = tid + 256*it; int rr = idx >> 6, cc = idx & 63;
            Ks[idx] = kb[(size_t)(k0+rr)*64 + cc];
            Vs[idx] = vb[(size_t)(k0+rr)*64 + cc];
        }
        __syncthreads();
        float s[8];
        #pragma unroll
        for (int j = 0; j < 8; j++) s[j] = 0.f;
        #pragma unroll
        for (int e4 = 0; e4 < 64; e4 += 4) {
            float q0v = Qs[r*65+e4+0], q1v = Qs[r*65+e4+1];
            float q2v = Qs[r*65+e4+2], q3v = Qs[r*65+e4+3];
            #pragma unroll
            for (int j = 0; j < 8; j++) {
                float4 kv = *(const float4*)&Ks[(quad*8+j)*64 + e4];
                s[j] += q0v*kv.x + q1v*kv.y + q2v*kv.z + q3v*kv.w;
            }
        }
        float lm = -1e30f;
        #pragma unroll
        for (int j = 0; j < 8; j++) { s[j] *= 0.125f; lm = fmaxf(lm, s[j]); }
        redM[r*4+quad] = lm;
        __syncthreads();
        float m_new = fmaxf(m_old,
            fmaxf(fmaxf(redM[r*4+0], redM[r*4+1]),
                  fmaxf(redM[r*4+2], redM[r*4+3])));
        float alpha = __expf(m_old - m_new);
        float lsum = 0.f;
        #pragma unroll
        for (int j = 0; j < 8; j++) {
            float p = __expf(s[j] - m_new);
            Ps[r*33 + quad*8 + j] = p;
            lsum += p;
        }
        redS[r*4+quad] = lsum;
        #pragma unroll
        for (int j = 0; j < 16; j++) acc[j] *= alpha;
        __syncthreads();
        l_old = l_old*alpha + (redS[r*4+0]+redS[r*4+1]+redS[r*4+2]+redS[r*4+3]);
        m_old = m_new;
        #pragma unroll 4
        for (int kc = 0; kc < 32; kc++) {
            float p = Ps[r*33 + kc];
            #pragma unroll
            for (int j4 = 0; j4 < 16; j4 += 4) {
                float4 vv = *(const float4*)&Vs[kc*64 + quad*16 + j4];
                acc[j4+0] += p*vv.x; acc[j4+1] += p*vv.y;
                acc[j4+2] += p*vv.z; acc[j4+3] += p*vv.w;
            }
        }
    }
    __syncthreads();
    float inv = 1.f / l_old;
    #pragma unroll
    for (int j = 0; j < 16; j++) Qs[r*65 + quad*16 + j] = acc[j] * inv;
    __syncthreads();
    int b = bh >> 3, h = bh & 7;
    float* xb = g_x + ((size_t)(b*Tc + q0))*Dc + h*64;
    for (int it = 0; it < 16; it++) {
        int idx = tid + 256*it; int rr = idx >> 6, cc = idx & 63;
        xb[(size_t)rr*Dc + cc] += Qs[rr*65+cc];   // residual add, exclusive region
    }
}

// ---------------- 128x128x8 SGEMM, fused epilogues -----------------
__device__ __forceinline__ float geluf(float x) {
    return 0.5f * x * (1.0f + erff(x * 0.70710678118654752f));
}

// MODE 0: C = gelu(A@B + bias)          (FC1)
// MODE 1: C = C + (A@B + bias)          (FC2, residual into g_x)
template<int MODE>
__global__ __launch_bounds__(256) void sgemm_kernel(
        const float* __restrict__ A, const float* __restrict__ Bw,
        const float* __restrict__ bias, float* __restrict__ C,
        int N, int K) {
    __shared__ float As[8][132];
    __shared__ float Bs[8][132];
    int tid = threadIdx.x;
    int tx = tid & 15, ty = tid >> 4;
    int m0 = blockIdx.y * 128, n0 = blockIdx.x * 128;
    float acc[8][8];
    #pragma unroll
    for (int i = 0; i < 8; i++)
        #pragma unroll
        for (int j = 0; j < 8; j++) acc[i][j] = 0.f;

    int arow = tid >> 1, ac4 = (tid & 1) * 4;
    int brow = tid >> 5, bc4 = (tid & 31) * 4;
    const float* Ap = A  + (size_t)(m0 + arow)*K + ac4;
    const float* Bp = Bw + (size_t)brow*N + n0 + bc4;

    for (int k0 = 0; k0 < K; k0 += 8) {
        float4 av = *(const float4*)(Ap + k0);
        float4 bv = *(const float4*)(Bp + (size_t)k0*N);
        As[ac4+0][arow] = av.x; As[ac4+1][arow] = av.y;
        As[ac4+2][arow] = av.z; As[ac4+3][arow] = av.w;
        *(float4*)&Bs[brow][bc4] = bv;
        __syncthreads();
        #pragma unroll
        for (int k = 0; k < 8; k++) {
            float a[8], bb[8];
            *(float4*)(a)    = *(const float4*)&As[k][ty*4];
            *(float4*)(a+4)  = *(const float4*)&As[k][64 + ty*4];
            *(float4*)(bb)   = *(const float4*)&Bs[k][tx*4];
            *(float4*)(bb+4) = *(const float4*)&Bs[k][64 + tx*4];
            #pragma unroll
            for (int i = 0; i < 8; i++)
                #pragma unroll
                for (int j = 0; j < 8; j++)
                    acc[i][j] += a[i]*bb[j];
        }
        __syncthreads();
    }
    #pragma unroll
    for (int i = 0; i < 8; i++) {
        int m = m0 + ((i < 4) ? (ty*4 + i) : (64 + ty*4 + i - 4));
        float* crow = C + (size_t)m*N + n0;
        #pragma unroll
        for (int hb = 0; hb < 2; hb++) {
            int nb = hb*64 + tx*4;
            float4 bbv = *(const float4*)(bias + n0 + nb);
            float4 rv;
            rv.x = acc[i][hb*4+0] + bbv.x;
            rv.y = acc[i][hb*4+1] + bbv.y;
            rv.z = acc[i][hb*4+2] + bbv.z;
            rv.w = acc[i][hb*4+3] + bbv.w;
            if (MODE == 0) {
                rv.x = geluf(rv.x); rv.y = geluf(rv.y);
                rv.z = geluf(rv.z); rv.w = geluf(rv.w);
            } else {
                float4 old = *(const float4*)(crow + nb);
                rv.x += old.x; rv.y += old.y; rv.z += old.z; rv.w += old.w;
            }
            *(float4*)(crow + nb) = rv;
        }
    }
}

// ---------------- classifier head ---------------------------------
__global__ __launch_bounds__(512) void head_kernel(
        const float* __restrict__ hW, const float* __restrict__ hb,
        float* __restrict__ out) {
    int w = threadIdx.x >> 5, lane = threadIdx.x & 31;   // 16 warps = 16 batches
    const float* xr = g_x + (size_t)w * Tc * Dc;         // token t=0
    float s = 0.f;
    for (int d = lane; d < Dc; d += 32) s += xr[d] * hW[d];
    #pragma unroll
    for (int o = 16; o; o >>= 1) s += __shfl_xor_sync(0xffffffffu, s, o);
    if (lane == 0) out[w] = 1.f / (1.f + expf(-(s + hb[0])));
}

// ---------------- launcher -----------------------------------------
extern "C" void kernel_launch(void* const* d_in, const int* in_sizes, int n_in,
                              void* d_out, int out_size) {
    const float* src  = (const float*)d_in[0];
    const float* embW = (const float*)d_in[1];
    const float* embb = (const float*)d_in[2];
    const float* cls  = (const float*)d_in[3];
    const float* ln1g = (const float*)d_in[4];
    const float* ln1b = (const float*)d_in[5];
    const float* Wq   = (const float*)d_in[6];
    const float* bq   = (const float*)d_in[7];
    const float* Wk   = (const float*)d_in[8];
    const float* bk   = (const float*)d_in[9];
    const float* Wv   = (const float*)d_in[10];
    const float* bv   = (const float*)d_in[11];
    const float* ln2g = (const float*)d_in[12];
    const float* ln2b = (const float*)d_in[13];
    const float* W1   = (const float*)d_in[14];
    const float* b1   = (const float*)d_in[15];
    const float* W2   = (const float*)d_in[16];
    const float* b2   = (const float*)d_in[17];
    const float* hW   = (const float*)d_in[18];
    const float* hb   = (const float*)d_in[19];
    float* out = (float*)d_out;

    float *ph, *pm1, *px;
    cudaGetSymbolAddress((void**)&ph,  g_h);
    cudaGetSymbolAddress((void**)&pm1, g_m1);
    cudaGetSymbolAddress((void**)&px,  g_x);

    pe_freq_kernel<<<1, 512>>>();
    embed_kernel<<<BTc, 128>>>(src, embW, embb, cls);
    for (int i = 0; i < NBc; i++) {
        ln_kernel<<<BTc, 128>>>(ln1g + i*Dc, ln1b + i*Dc);
        qkv_kernel<<<dim3(Tc/64, Bc*Hc, 3), 256>>>(
            Wq + (size_t)i*Hc*DHc*DHc, bq + (size_t)i*Hc*DHc,
            Wk + (size_t)i*Hc*DHc*DHc, bk + (size_t)i*Hc*DHc,
            Wv + (size_t)i*Hc*DHc*DHc, bv + (size_t)i*Hc*DHc);
        attn_kernel<<<dim3(Tc/64, Bc*Hc), 256>>>();
        ln_kernel<<<BTc, 128>>>(ln2g + i*Dc, ln2b + i*Dc);
        sgemm_kernel<0><<<dim3(MLPc/128, BTc/128), 256>>>(
            ph, W1 + (size_t)i*Dc*MLPc, b1 + (size_t)i*MLPc, pm1, MLPc, Dc);
        sgemm_kernel<1><<<dim3(Dc/128, BTc/128), 256>>>(
            pm1, W2 + (size_t)i*MLPc*Dc, b2 + (size_t)i*Dc, px, Dc, MLPc);
    }
    head_kernel<<<1, 512>>>(hW, hb, out);
}

// round 11
// speedup vs baseline: 1.0559x; 1.0011x over previous
#include <cuda_runtime.h>
#include <math.h>

// Problem dims
#define Bc   16
#define Sc   511
#define Fc   128
#define Dc   512
#define Hc   8
#define DHc  64
#define NBc  6
#define MLPc 2048
#define Tc   512
#define BTc  (Bc*Tc)   // 8192

// ---------------- scratch (no allocations allowed) ----------------
__device__ float g_x[(size_t)BTc*Dc];        // residual stream  [B*T, D]
__device__ float g_h[(size_t)BTc*Dc];        // LN output        [B*T, D]
__device__ float g_q[(size_t)Bc*Hc*Tc*DHc];  // [B*H, T, DH]
__device__ float g_k[(size_t)Bc*Hc*Tc*DHc];
__device__ float g_v[(size_t)Bc*Hc*Tc*DHc];
__device__ float g_m1[(size_t)BTc*MLPc];     // MLP hidden [B*T, 4D]
__device__ float g_freq[Dc];                 // pos-emb denominators

// ---------------- positional-embedding frequencies (fp64, tiny) ----
__global__ void pe_freq_kernel() {
    int d  = threadIdx.x;
    int je = d & ~1;
    g_freq[d] = (float)pow(10000.0, (double)je / 512.0);
}

// ---------------- embedding: x = src@embW + embb + PE; cls row -----
__global__ __launch_bounds__(128) void embed_kernel(
        const float* __restrict__ src, const float* __restrict__ Wemb,
        const float* __restrict__ bemb, const float* __restrict__ cls) {
    int row = blockIdx.x;               // 0..8191 = b*512 + t
    int b = row >> 9, t = row & 511;
    int tid = threadIdx.x;
    float* xo = g_x + (size_t)row * Dc;
    if (t == 0) {
        #pragma unroll
        for (int kk = 0; kk < 4; kk++) {
            int d = tid + 128*kk;
            xo[d] = cls[d] + ((d & 1) ? 1.0f : 0.0f);  // cos(0)=1, sin(0)=0
        }
        return;
    }
    __shared__ float ss[128];
    ss[tid] = src[((size_t)b*Sc + (t-1))*Fc + tid];
    __syncthreads();
    #pragma unroll
    for (int kk = 0; kk < 4; kk++) {
        int d = tid + 128*kk;
        float acc = bemb[d];
        #pragma unroll 8
        for (int f = 0; f < 128; f++) acc += ss[f] * Wemb[(size_t)f*Dc + d];
        float ang = (float)t / g_freq[d];
        acc += (d & 1) ? cosf(ang) : sinf(ang);
        xo[d] = acc;
    }
}

// ---------------- LayerNorm: g_h = LN(g_x)*g + b -------------------
__global__ __launch_bounds__(128) void ln_kernel(
        const float* __restrict__ gam, const float* __restrict__ bet) {
    int row = blockIdx.x, tid = threadIdx.x;
    const float4* xin = (const float4*)(g_x + (size_t)row*Dc);
    float4 v = xin[tid];
    float s  = v.x+v.y+v.z+v.w;
    float sq = v.x*v.x + v.y*v.y + v.z*v.z + v.w*v.w;
    #pragma unroll
    for (int o = 16; o; o >>= 1) {
        s  += __shfl_xor_sync(0xffffffffu, s,  o);
        sq += __shfl_xor_sync(0xffffffffu, sq, o);
    }
    __shared__ float sm[8];
    if ((tid & 31) == 0) { sm[tid>>5] = s; sm[4 + (tid>>5)] = sq; }
    __syncthreads();
    s  = sm[0]+sm[1]+sm[2]+sm[3];
    sq = sm[4]+sm[5]+sm[6]+sm[7];
    float mean = s * (1.f/512.f);
    float var  = sq * (1.f/512.f) - mean*mean;
    float rstd = rsqrtf(var + 1e-5f);
    float4 g4 = ((const float4*)gam)[tid];
    float4 b4 = ((const float4*)bet)[tid];
    float4 o;
    o.x = (v.x-mean)*rstd*g4.x + b4.x;
    o.y = (v.y-mean)*rstd*g4.y + b4.y;
    o.z = (v.z-mean)*rstd*g4.z + b4.z;
    o.w = (v.w-mean)*rstd*g4.w + b4.w;
    ((float4*)(g_h + (size_t)row*Dc))[tid] = o;
}

// ---------------- per-head QKV projection (64x64x64 tiles) ---------
__global__ __launch_bounds__(256) void qkv_kernel(
        const float* __restrict__ Wq, const float* __restrict__ bq,
        const float* __restrict__ Wk, const float* __restrict__ bk,
        const float* __restrict__ Wv, const float* __restrict__ bv) {
    __shared__ float Hs[64*65];   // input tile, padded (lane-varying reads)
    __shared__ float Ws[64*64];   // weights, unpadded (warp-uniform reads)
    int tid = threadIdx.x;
    int bh  = blockIdx.y; int b = bh >> 3, h = bh & 7;
    int t0  = blockIdx.x * 64;
    int z   = blockIdx.z;
    const float* W    = (z==0 ? Wq : (z==1 ? Wk : Wv)) + (size_t)h*4096;
    const float* bias = (z==0 ? bq : (z==1 ? bk : bv)) + h*64;
    float*       out  = (z==0 ? g_q : (z==1 ? g_k : g_v)) + (size_t)bh*Tc*64;

    for (int it = 0; it < 16; it++) {
        int idx = tid + 256*it; int rr = idx >> 6, cc = idx & 63;
        Hs[rr*65+cc] = g_h[((size_t)b*Tc + t0 + rr)*Dc + h*64 + cc];
        Ws[idx] = W[idx];
    }
    __syncthreads();
    int r = tid & 63, quad = tid >> 6;
    float acc[16];
    #pragma unroll
    for (int j = 0; j < 16; j++) acc[j] = bias[quad*16 + j];
    for (int d = 0; d < 64; d++) {
        float hv = Hs[r*65 + d];
        #pragma unroll
        for (int j4 = 0; j4 < 16; j4 += 4) {
            float4 wv = *(const float4*)&Ws[d*64 + quad*16 + j4];
            acc[j4+0] += hv*wv.x; acc[j4+1] += hv*wv.y;
            acc[j4+2] += hv*wv.z; acc[j4+3] += hv*wv.w;
        }
    }
    __syncthreads();
    #pragma unroll
    for (int j = 0; j < 16; j++) Hs[r*65 + quad*16 + j] = acc[j];
    __syncthreads();
    for (int it = 0; it < 16; it++) {
        int idx = tid + 256*it; int rr = idx >> 6, cc = idx & 63;
        out[(size_t)(t0+rr)*64 + cc] = Hs[rr*65+cc];
    }
}

// ---------------- flash attention + residual add -------------------
// 64 queries per CTA, 32-key tiles, online softmax. All-static smem (<48KB).
__global__ __launch_bounds__(256) void attn_kernel() {
    __shared__ float Qs[64*65];   // padded: lane-varying scalar reads
    __shared__ float Ks[32*64];   // unpadded: warp-uniform float4 reads
    __shared__ float Vs[32*64];   // unpadded: warp-uniform float4 reads
    __shared__ float Ps[64*33];   // padded: lane-varying scalar reads
    __shared__ float redM[64*4];
    __shared__ float redS[64*4];
    int tid = threadIdx.x;
    int bh  = blockIdx.y; int q0 = blockIdx.x * 64;
    const float* qb = g_q + (size_t)bh*Tc*64;
    const float* kb = g_k + (size_t)bh*Tc*64;
    const float* vb = g_v + (size_t)bh*Tc*64;

    for (int it = 0; it < 16; it++) {
        int idx = tid + 256*it; int rr = idx >> 6, cc = idx & 63;
        Qs[rr*65+cc] = qb[(size_t)(q0+rr)*64 + cc];
    }
    int r = tid & 63, quad = tid >> 6;
    float m_old = -1e30f, l_old = 0.f;
    float acc[16];
    #pragma unroll
    for (int j = 0; j < 16; j++) acc[j] = 0.f;

    for (int kt = 0; kt < 16; kt++) {
        __syncthreads();                       // prev tile's Ps/Vs reads done
        int k0 = kt * 32;
        for (int it = 0; it < 8; it++) {
            int idx = tid + 256*it; int rr = idx >> 6, cc = idx & 63;
            Ks[idx] = kb[(size_t)(k0+rr)*64 + cc];
            Vs[idx] = vb[(size_t)(k0+rr)*64 + cc];
        }
        __syncthreads();
        float s[8];
        #pragma unroll
        for (int j = 0; j < 8; j++) s[j] = 0.f;
        #pragma unroll
        for (int e4 = 0; e4 < 64; e4 += 4) {
            float q0v = Qs[r*65+e4+0], q1v = Qs[r*65+e4+1];
            float q2v = Qs[r*65+e4+2], q3v = Qs[r*65+e4+3];
            #pragma unroll
            for (int j = 0; j < 8; j++) {
                float4 kv = *(const float4*)&Ks[(quad*8+j)*64 + e4];
                s[j] += q0v*kv.x + q1v*kv.y + q2v*kv.z + q3v*kv.w;
            }
        }
        float lm = -1e30f;
        #pragma unroll
        for (int j = 0; j < 8; j++) { s[j] *= 0.125f; lm = fmaxf(lm, s[j]); }
        redM[r*4+quad] = lm;
        __syncthreads();
        float m_new = fmaxf(m_old,
            fmaxf(fmaxf(redM[r*4+0], redM[r*4+1]),
                  fmaxf(redM[r*4+2], redM[r*4+3])));
        float alpha = __expf(m_old - m_new);
        float lsum = 0.f;
        #pragma unroll
        for (int j = 0; j < 8; j++) {
            float p = __expf(s[j] - m_new);
            Ps[r*33 + quad*8 + j] = p;
            lsum += p;
        }
        redS[r*4+quad] = lsum;
        #pragma unroll
        for (int j = 0; j < 16; j++) acc[j] *= alpha;
        __syncthreads();
        l_old = l_old*alpha + (redS[r*4+0]+redS[r*4+1]+redS[r*4+2]+redS[r*4+3]);
        m_old = m_new;
        #pragma unroll 4
        for (int kc = 0; kc < 32; kc++) {
            float p = Ps[r*33 + kc];
            #pragma unroll
            for (int j4 = 0; j4 < 16; j4 += 4) {
                float4 vv = *(const float4*)&Vs[kc*64 + quad*16 + j4];
                acc[j4+0] += p*vv.x; acc[j4+1] += p*vv.y;
                acc[j4+2] += p*vv.z; acc[j4+3] += p*vv.w;
            }
        }
    }
    __syncthreads();
    float inv = 1.f / l_old;
    #pragma unroll
    for (int j = 0; j < 16; j++) Qs[r*65 + quad*16 + j] = acc[j] * inv;
    __syncthreads();
    int b = bh >> 3, h = bh & 7;
    float* xb = g_x + ((size_t)(b*Tc + q0))*Dc + h*64;
    for (int it = 0; it < 16; it++) {
        int idx = tid + 256*it; int rr = idx >> 6, cc = idx & 63;
        xb[(size_t)rr*Dc + cc] += Qs[rr*65+cc];   // residual add, exclusive region
    }
}

// ---------------- 128x128x8 SGEMM, fused epilogues -----------------
__device__ __forceinline__ float geluf(float x) {
    return 0.5f * x * (1.0f + erff(x * 0.70710678118654752f));
}

// MODE 0: C = gelu(A@B + bias)          (FC1)
// MODE 1: C = C + (A@B + bias)          (FC2, residual into g_x)
template<int MODE>
__global__ __launch_bounds__(256) void sgemm_kernel(
        const float* __restrict__ A, const float* __restrict__ Bw,
        const float* __restrict__ bias, float* __restrict__ C,
        int N, int K) {
    __shared__ float As[8][132];
    __shared__ float Bs[8][132];
    int tid = threadIdx.x;
    int tx = tid & 15, ty = tid >> 4;
    int m0 = blockIdx.y * 128, n0 = blockIdx.x * 128;
    float acc[8][8];
    #pragma unroll
    for (int i = 0; i < 8; i++)
        #pragma unroll
        for (int j = 0; j < 8; j++) acc[i][j] = 0.f;

    int arow = tid >> 1, ac4 = (tid & 1) * 4;
    int brow = tid >> 5, bc4 = (tid & 31) * 4;
    const float* Ap = A  + (size_t)(m0 + arow)*K + ac4;
    const float* Bp = Bw + (size_t)brow*N + n0 + bc4;

    for (int k0 = 0; k0 < K; k0 += 8) {
        float4 av = *(const float4*)(Ap + k0);
        float4 bv = *(const float4*)(Bp + (size_t)k0*N);
        As[ac4+0][arow] = av.x; As[ac4+1][arow] = av.y;
        As[ac4+2][arow] = av.z; As[ac4+3][arow] = av.w;
        *(float4*)&Bs[brow][bc4] = bv;
        __syncthreads();
        #pragma unroll
        for (int k = 0; k < 8; k++) {
            float a[8], bb[8];
            *(float4*)(a)    = *(const float4*)&As[k][ty*4];
            *(float4*)(a+4)  = *(const float4*)&As[k][64 + ty*4];
            *(float4*)(bb)   = *(const float4*)&Bs[k][tx*4];
            *(float4*)(bb+4) = *(const float4*)&Bs[k][64 + tx*4];
            #pragma unroll
            for (int i = 0; i < 8; i++)
                #pragma unroll
                for (int j = 0; j < 8; j++)
                    acc[i][j] += a[i]*bb[j];
        }
        __syncthreads();
    }
    #pragma unroll
    for (int i = 0; i < 8; i++) {
        int m = m0 + ((i < 4) ? (ty*4 + i) : (64 + ty*4 + i - 4));
        float* crow = C + (size_t)m*N + n0;
        #pragma unroll
        for (int hb = 0; hb < 2; hb++) {
            int nb = hb*64 + tx*4;
            float4 bbv = *(const float4*)(bias + n0 + nb);
            float4 rv;
            rv.x = acc[i][hb*4+0] + bbv.x;
            rv.y = acc[i][hb*4+1] + bbv.y;
            rv.z = acc[i][hb*4+2] + bbv.z;
            rv.w = acc[i][hb*4+3] + bbv.w;
            if (MODE == 0) {
                rv.x = geluf(rv.x); rv.y = geluf(rv.y);
                rv.z = geluf(rv.z); rv.w = geluf(rv.w);
            } else {
                float4 old = *(const float4*)(crow + nb);
                rv.x += old.x; rv.y += old.y; rv.z += old.z; rv.w += old.w;
            }
            *(float4*)(crow + nb) = rv;
        }
    }
}

// ---------------- classifier head ---------------------------------
__global__ __launch_bounds__(512) void head_kernel(
        const float* __restrict__ hW, const float* __restrict__ hb,
        float* __restrict__ out) {
    int w = threadIdx.x >> 5, lane = threadIdx.x & 31;   // 16 warps = 16 batches
    const float* xr = g_x + (size_t)w * Tc * Dc;         // token t=0
    float s = 0.f;
    for (int d = lane; d < Dc; d += 32) s += xr[d] * hW[d];
    #pragma unroll
    for (int o = 16; o; o >>= 1) s += __shfl_xor_sync(0xffffffffu, s, o);
    if (lane == 0) out[w] = 1.f / (1.f + expf(-(s + hb[0])));
}

// ---------------- launcher -----------------------------------------
extern "C" void kernel_launch(void* const* d_in, const int* in_sizes, int n_in,
                              void* d_out, int out_size) {
    const float* src  = (const float*)d_in[0];
    const float* embW = (const float*)d_in[1];
    const float* embb = (const float*)d_in[2];
    const float* cls  = (const float*)d_in[3];
    const float* ln1g = (const float*)d_in[4];
    const float* ln1b = (const float*)d_in[5];
    const float* Wq   = (const float*)d_in[6];
    const float* bq   = (const float*)d_in[7];
    const float* Wk   = (const float*)d_in[8];
    const float* bk   = (const float*)d_in[9];
    const float* Wv   = (const float*)d_in[10];
    const float* bv   = (const float*)d_in[11];
    const float* ln2g = (const float*)d_in[12];
    const float* ln2b = (const float*)d_in[13];
    const float* W1   = (const float*)d_in[14];
    const float* b1   = (const float*)d_in[15];
    const float* W2   = (const float*)d_in[16];
    const float* b2   = (const float*)d_in[17];
    const float* hW   = (const float*)d_in[18];
    const float* hb   = (const float*)d_in[19];
    float* out = (float*)d_out;

    float *ph, *pm1, *px;
    cudaGetSymbolAddress((void**)&ph,  g_h);
    cudaGetSymbolAddress((void**)&pm1, g_m1);
    cudaGetSymbolAddress((void**)&px,  g_x);

    pe_freq_kernel<<<1, 512>>>();
    embed_kernel<<<BTc, 128>>>(src, embW, embb, cls);
    for (int i = 0; i < NBc; i++) {
        ln_kernel<<<BTc, 128>>>(ln1g + i*Dc, ln1b + i*Dc);
        qkv_kernel<<<dim3(Tc/64, Bc*Hc, 3), 256>>>(
            Wq + (size_t)i*Hc*DHc*DHc, bq + (size_t)i*Hc*DHc,
            Wk + (size_t)i*Hc*DHc*DHc, bk + (size_t)i*Hc*DHc,
            Wv + (size_t)i*Hc*DHc*DHc, bv + (size_t)i*Hc*DHc);
        attn_kernel<<<dim3(Tc/64, Bc*Hc), 256>>>();
        ln_kernel<<<BTc, 128>>>(ln2g + i*Dc, ln2b + i*Dc);
        sgemm_kernel<0><<<dim3(MLPc/128, BTc/128), 256>>>(
            ph, W1 + (size_t)i*Dc*MLPc, b1 + (size_t)i*MLPc, pm1, MLPc, Dc);
        sgemm_kernel<1><<<dim3(Dc/128, BTc/128), 256>>>(
            pm1, W2 + (size_t)i*MLPc*Dc, b2 + (size_t)i*Dc, px, Dc, MLPc);
    }
    head_kernel<<<1, 512>>>(hW, hb, out);
}

// round 12
// speedup vs baseline: 1.0564x; 1.0005x over previous
#include <cuda_runtime.h>
#include <math.h>

// Problem dims
#define Bc   16
#define Sc   511
#define Fc   128
#define Dc   512
#define Hc   8
#define DHc  64
#define NBc  6
#define MLPc 2048
#define Tc   512
#define BTc  (Bc*Tc)   // 8192

// ---------------- scratch (no allocations allowed) ----------------
__device__ float g_x[(size_t)BTc*Dc];        // residual stream  [B*T, D]
__device__ float g_h[(size_t)BTc*Dc];        // LN output        [B*T, D]
__device__ float g_q[(size_t)Bc*Hc*Tc*DHc];  // [B*H, T, DH]
__device__ float g_k[(size_t)Bc*Hc*Tc*DHc];
__device__ float g_v[(size_t)Bc*Hc*Tc*DHc];
__device__ float g_m1[(size_t)BTc*MLPc];     // MLP hidden [B*T, 4D]
__device__ float g_freq[Dc];                 // pos-emb denominators

// ---------------- positional-embedding frequencies (fp64, tiny) ----
__global__ void pe_freq_kernel() {
    int d  = threadIdx.x;
    int je = d & ~1;
    g_freq[d] = (float)pow(10000.0, (double)je / 512.0);
}

// ---------------- embedding: x = src@embW + embb + PE; cls row -----
__global__ __launch_bounds__(128) void embed_kernel(
        const float* __restrict__ src, const float* __restrict__ Wemb,
        const float* __restrict__ bemb, const float* __restrict__ cls) {
    int row = blockIdx.x;               // 0..8191 = b*512 + t
    int b = row >> 9, t = row & 511;
    int tid = threadIdx.x;
    float* xo = g_x + (size_t)row * Dc;
    if (t == 0) {
        #pragma unroll
        for (int kk = 0; kk < 4; kk++) {
            int d = tid + 128*kk;
            xo[d] = cls[d] + ((d & 1) ? 1.0f : 0.0f);  // cos(0)=1, sin(0)=0
        }
        return;
    }
    __shared__ float ss[128];
    ss[tid] = src[((size_t)b*Sc + (t-1))*Fc + tid];
    __syncthreads();
    #pragma unroll
    for (int kk = 0; kk < 4; kk++) {
        int d = tid + 128*kk;
        float acc = bemb[d];
        #pragma unroll 8
        for (int f = 0; f < 128; f++) acc += ss[f] * Wemb[(size_t)f*Dc + d];
        float ang = (float)t / g_freq[d];
        acc += (d & 1) ? cosf(ang) : sinf(ang);
        xo[d] = acc;
    }
}

// ---------------- LayerNorm: g_h = LN(g_x)*g + b -------------------
__global__ __launch_bounds__(128) void ln_kernel(
        const float* __restrict__ gam, const float* __restrict__ bet) {
    int row = blockIdx.x, tid = threadIdx.x;
    const float4* xin = (const float4*)(g_x + (size_t)row*Dc);
    float4 v = xin[tid];
    float s  = v.x+v.y+v.z+v.w;
    float sq = v.x*v.x + v.y*v.y + v.z*v.z + v.w*v.w;
    #pragma unroll
    for (int o = 16; o; o >>= 1) {
        s  += __shfl_xor_sync(0xffffffffu, s,  o);
        sq += __shfl_xor_sync(0xffffffffu, sq, o);
    }
    __shared__ float sm[8];
    if ((tid & 31) == 0) { sm[tid>>5] = s; sm[4 + (tid>>5)] = sq; }
    __syncthreads();
    s  = sm[0]+sm[1]+sm[2]+sm[3];
    sq = sm[4]+sm[5]+sm[6]+sm[7];
    float mean = s * (1.f/512.f);
    float var  = sq * (1.f/512.f) - mean*mean;
    float rstd = rsqrtf(var + 1e-5f);
    float4 g4 = ((const float4*)gam)[tid];
    float4 b4 = ((const float4*)bet)[tid];
    float4 o;
    o.x = (v.x-mean)*rstd*g4.x + b4.x;
    o.y = (v.y-mean)*rstd*g4.y + b4.y;
    o.z = (v.z-mean)*rstd*g4.z + b4.z;
    o.w = (v.w-mean)*rstd*g4.w + b4.w;
    ((float4*)(g_h + (size_t)row*Dc))[tid] = o;
}

// ---------------- per-head QKV projection (64x64x64 tiles) ---------
__global__ __launch_bounds__(256) void qkv_kernel(
        const float* __restrict__ Wq, const float* __restrict__ bq,
        const float* __restrict__ Wk, const float* __restrict__ bk,
        const float* __restrict__ Wv, const float* __restrict__ bv) {
    __shared__ float Hs[64*65];   // input tile, padded (lane-varying reads)
    __shared__ float Ws[64*64];   // weights, unpadded (warp-uniform reads)
    int tid = threadIdx.x;
    int bh  = blockIdx.y; int b = bh >> 3, h = bh & 7;
    int t0  = blockIdx.x * 64;
    int z   = blockIdx.z;
    const float* W    = (z==0 ? Wq : (z==1 ? Wk : Wv)) + (size_t)h*4096;
    const float* bias = (z==0 ? bq : (z==1 ? bk : bv)) + h*64;
    float*       out  = (z==0 ? g_q : (z==1 ? g_k : g_v)) + (size_t)bh*Tc*64;

    for (int it = 0; it < 16; it++) {
        int idx = tid + 256*it; int rr = idx >> 6, cc = idx & 63;
        Hs[rr*65+cc] = g_h[((size_t)b*Tc + t0 + rr)*Dc + h*64 + cc];
        Ws[idx] = W[idx];
    }
    __syncthreads();
    int r = tid & 63, quad = tid >> 6;
    float acc[16];
    #pragma unroll
    for (int j = 0; j < 16; j++) acc[j] = bias[quad*16 + j];
    for (int d = 0; d < 64; d++) {
        float hv = Hs[r*65 + d];
        #pragma unroll
        for (int j4 = 0; j4 < 16; j4 += 4) {
            float4 wv = *(const float4*)&Ws[d*64 + quad*16 + j4];
            acc[j4+0] += hv*wv.x; acc[j4+1] += hv*wv.y;
            acc[j4+2] += hv*wv.z; acc[j4+3] += hv*wv.w;
        }
    }
    __syncthreads();
    #pragma unroll
    for (int j = 0; j < 16; j++) Hs[r*65 + quad*16 + j] = acc[j];
    __syncthreads();
    for (int it = 0; it < 16; it++) {
        int idx = tid + 256*it; int rr = idx >> 6, cc = idx & 63;
        out[(size_t)(t0+rr)*64 + cc] = Hs[rr*65+cc];
    }
}

// ---------------- flash attention + residual add -------------------
// 64 queries per CTA, 32-key tiles, online softmax. All-static smem (<48KB).
__global__ __launch_bounds__(256) void attn_kernel() {
    __shared__ float Qs[64*65];   // padded: lane-varying scalar reads
    __shared__ float Ks[32*64];   // unpadded: warp-uniform float4 reads
    __shared__ float Vs[32*64];   // unpadded: warp-uniform float4 reads
    __shared__ float Ps[64*33];   // padded: lane-varying scalar reads
    __shared__ float redM[64*4];
    __shared__ float redS[64*4];
    int tid = threadIdx.x;
    int bh  = blockIdx.y; int q0 = blockIdx.x * 64;
    const float* qb = g_q + (size_t)bh*Tc*64;
    const float* kb = g_k + (size_t)bh*Tc*64;
    const float* vb = g_v + (size_t)bh*Tc*64;

    for (int it = 0; it < 16; it++) {
        int idx = tid + 256*it; int rr = idx >> 6, cc = idx & 63;
        Qs[rr*65+cc] = qb[(size_t)(q0+rr)*64 + cc];
    }
    int r = tid & 63, quad = tid >> 6;
    float m_old = -1e30f, l_old = 0.f;
    float acc[16];
    #pragma unroll
    for (int j = 0; j < 16; j++) acc[j] = 0.f;

    for (int kt = 0; kt < 16; kt++) {
        __syncthreads();                       // prev tile's Ps/Vs reads done
        int k0 = kt * 32;
        for (int it = 0; it < 8; it++) {
            int idx = tid + 256*it; int rr = idx >> 6, cc = idx & 63;
            Ks[idx] = kb[(size_t)(k0+rr)*64 + cc];
            Vs[idx] = vb[(size_t)(k0+rr)*64 + cc];
        }
        __syncthreads();
        float s[8];
        #pragma unroll
        for (int j = 0; j < 8; j++) s[j] = 0.f;
        #pragma unroll
        for (int e4 = 0; e4 < 64; e4 += 4) {
            float q0v = Qs[r*65+e4+0], q1v = Qs[r*65+e4+1];
            float q2v = Qs[r*65+e4+2], q3v = Qs[r*65+e4+3];
            #pragma unroll
            for (int j = 0; j < 8; j++) {
                float4 kv = *(const float4*)&Ks[(quad*8+j)*64 + e4];
                s[j] += q0v*kv.x + q1v*kv.y + q2v*kv.z + q3v*kv.w;
            }
        }
        float lm = -1e30f;
        #pragma unroll
        for (int j = 0; j < 8; j++) { s[j] *= 0.125f; lm = fmaxf(lm, s[j]); }
        redM[r*4+quad] = lm;
        __syncthreads();
        float m_new = fmaxf(m_old,
            fmaxf(fmaxf(redM[r*4+0], redM[r*4+1]),
                  fmaxf(redM[r*4+2], redM[r*4+3])));
        float alpha = __expf(m_old - m_new);
        float lsum = 0.f;
        #pragma unroll
        for (int j = 0; j < 8; j++) {
            float p = __expf(s[j] - m_new);
            Ps[r*33 + quad*8 + j] = p;
            lsum += p;
        }
        redS[r*4+quad] = lsum;
        #pragma unroll
        for (int j = 0; j < 16; j++) acc[j] *= alpha;
        __syncthreads();
        l_old = l_old*alpha + (redS[r*4+0]+redS[r*4+1]+redS[r*4+2]+redS[r*4+3]);
        m_old = m_new;
        #pragma unroll 4
        for (int kc = 0; kc < 32; kc++) {
            float p = Ps[r*33 + kc];
            #pragma unroll
            for (int j4 = 0; j4 < 16; j4 += 4) {
                float4 vv = *(const float4*)&Vs[kc*64 + quad*16 + j4];
                acc[j4+0] += p*vv.x; acc[j4+1] += p*vv.y;
                acc[j4+2] += p*vv.z; acc[j4+3] += p*vv.w;
            }
        }
    }
    __syncthreads();
    float inv = 1.f / l_old;
    #pragma unroll
    for (int j = 0; j < 16; j++) Qs[r*65 + quad*16 + j] = acc[j] * inv;
    __syncthreads();
    int b = bh >> 3, h = bh & 7;
    float* xb = g_x + ((size_t)(b*Tc + q0))*Dc + h*64;
    for (int it = 0; it < 16; it++) {
        int idx = tid + 256*it; int rr = idx >> 6, cc = idx & 63;
        xb[(size_t)rr*Dc + cc] += Qs[rr*65+cc];   // residual add, exclusive region
    }
}

// ---------------- 128x128x8 SGEMM, fused epilogues -----------------
__device__ __forceinline__ float geluf(float x) {
    return 0.5f * x * (1.0f + erff(x * 0.70710678118654752f));
}

// MODE 0: C = gelu(A@B + bias)          (FC1)
// MODE 1: C = C + (A@B + bias)          (FC2, residual into g_x)
template<int MODE>
__global__ __launch_bounds__(256) void sgemm_kernel(
        const float* __restrict__ A, const float* __restrict__ Bw,
        const float* __restrict__ bias, float* __restrict__ C,
        int N, int K) {
    __shared__ float As[8][132];
    __shared__ float Bs[8][132];
    int tid = threadIdx.x;
    int tx = tid & 15, ty = tid >> 4;
    int m0 = blockIdx.y * 128, n0 = blockIdx.x * 128;
    float acc[8][8];
    #pragma unroll
    for (int i = 0; i < 8; i++)
        #pragma unroll
        for (int j = 0; j < 8; j++) acc[i][j] = 0.f;

    int arow = tid >> 1, ac4 = (tid & 1) * 4;
    int brow = tid >> 5, bc4 = (tid & 31) * 4;
    const float* Ap = A  + (size_t)(m0 + arow)*K + ac4;
    const float* Bp = Bw + (size_t)brow*N + n0 + bc4;

    for (int k0 = 0; k0 < K; k0 += 8) {
        float4 av = *(const float4*)(Ap + k0);
        float4 bv = *(const float4*)(Bp + (size_t)k0*N);
        As[ac4+0][arow] = av.x; As[ac4+1][arow] = av.y;
        As[ac4+2][arow] = av.z; As[ac4+3][arow] = av.w;
        *(float4*)&Bs[brow][bc4] = bv;
        __syncthreads();
        #pragma unroll
        for (int k = 0; k < 8; k++) {
            float a[8], bb[8];
            *(float4*)(a)    = *(const float4*)&As[k][ty*4];
            *(float4*)(a+4)  = *(const float4*)&As[k][64 + ty*4];
            *(float4*)(bb)   = *(const float4*)&Bs[k][tx*4];
            *(float4*)(bb+4) = *(const float4*)&Bs[k][64 + tx*4];
            #pragma unroll
            for (int i = 0; i < 8; i++)
                #pragma unroll
                for (int j = 0; j < 8; j++)
                    acc[i][j] += a[i]*bb[j];
        }
        __syncthreads();
    }
    #pragma unroll
    for (int i = 0; i < 8; i++) {
        int m = m0 + ((i < 4) ? (ty*4 + i) : (64 + ty*4 + i - 4));
        float* crow = C + (size_t)m*N + n0;
        #pragma unroll
        for (int hb = 0; hb < 2; hb++) {
            int nb = hb*64 + tx*4;
            float4 bbv = *(const float4*)(bias + n0 + nb);
            float4 rv;
            rv.x = acc[i][hb*4+0] + bbv.x;
            rv.y = acc[i][hb*4+1] + bbv.y;
            rv.z = acc[i][hb*4+2] + bbv.z;
            rv.w = acc[i][hb*4+3] + bbv.w;
            if (MODE == 0) {
                rv.x = geluf(rv.x); rv.y = geluf(rv.y);
                rv.z = geluf(rv.z); rv.w = geluf(rv.w);
            } else {
                float4 old = *(const float4*)(crow + nb);
                rv.x += old.x; rv.y += old.y; rv.z += old.z; rv.w += old.w;
            }
            *(float4*)(crow + nb) = rv;
        }
    }
}

// ---------------- classifier head ---------------------------------
__global__ __launch_bounds__(512) void head_kernel(
        const float* __restrict__ hW, const float* __restrict__ hb,
        float* __restrict__ out) {
    int w = threadIdx.x >> 5, lane = threadIdx.x & 31;   // 16 warps = 16 batches
    const float* xr = g_x + (size_t)w * Tc * Dc;         // token t=0
    float s = 0.f;
    for (int d = lane; d < Dc; d += 32) s += xr[d] * hW[d];
    #pragma unroll
    for (int o = 16; o; o >>= 1) s += __shfl_xor_sync(0xffffffffu, s, o);
    if (lane == 0) out[w] = 1.f / (1.f + expf(-(s + hb[0])));
}

// ---------------- launcher -----------------------------------------
extern "C" void kernel_launch(void* const* d_in, const int* in_sizes, int n_in,
                              void* d_out, int out_size) {
    const float* src  = (const float*)d_in[0];
    const float* embW = (const float*)d_in[1];
    const float* embb = (const float*)d_in[2];
    const float* cls  = (const float*)d_in[3];
    const float* ln1g = (const float*)d_in[4];
    const float* ln1b = (const float*)d_in[5];
    const float* Wq   = (const float*)d_in[6];
    const float* bq   = (const float*)d_in[7];
    const float* Wk   = (const float*)d_in[8];
    const float* bk   = (const float*)d_in[9];
    const float* Wv   = (const float*)d_in[10];
    const float* bv   = (const float*)d_in[11];
    const float* ln2g = (const float*)d_in[12];
    const float* ln2b = (const float*)d_in[13];
    const float* W1   = (const float*)d_in[14];
    const float* b1   = (const float*)d_in[15];
    const float* W2   = (const float*)d_in[16];
    const float* b2   = (const float*)d_in[17];
    const float* hW   = (const float*)d_in[18];
    const float* hb   = (const float*)d_in[19];
    float* out = (float*)d_out;

    float *ph, *pm1, *px;
    cudaGetSymbolAddress((void**)&ph,  g_h);
    cudaGetSymbolAddress((void**)&pm1, g_m1);
    cudaGetSymbolAddress((void**)&px,  g_x);

    pe_freq_kernel<<<1, 512>>>();
    embed_kernel<<<BTc, 128>>>(src, embW, embb, cls);
    for (int i = 0; i < NBc; i++) {
        ln_kernel<<<BTc, 128>>>(ln1g + i*Dc, ln1b + i*Dc);
        qkv_kernel<<<dim3(Tc/64, Bc*Hc, 3), 256>>>(
            Wq + (size_t)i*Hc*DHc*DHc, bq + (size_t)i*Hc*DHc,
            Wk + (size_t)i*Hc*DHc*DHc, bk + (size_t)i*Hc*DHc,
            Wv + (size_t)i*Hc*DHc*DHc, bv + (size_t)i*Hc*DHc);
        attn_kernel<<<dim3(Tc/64, Bc*Hc), 256>>>();
        ln_kernel<<<BTc, 128>>>(ln2g + i*Dc, ln2b + i*Dc);
        sgemm_kernel<0><<<dim3(MLPc/128, BTc/128), 256>>>(
            ph, W1 + (size_t)i*Dc*MLPc, b1 + (size_t)i*MLPc, pm1, MLPc, Dc);
        sgemm_kernel<1><<<dim3(Dc/128, BTc/128), 256>>>(
            pm1, W2 + (size_t)i*MLPc*Dc, b2 + (size_t)i*Dc, px, Dc, MLPc);
    }
    head_kernel<<<1, 512>>>(hW, hb, out);
}

// round 14
// speedup vs baseline: 1.7705x; 1.6759x over previous
#include <cuda_runtime.h>
#include <math.h>
#include <stdint.h>

// Problem dims
#define Bc   16
#define Sc   511
#define Fc   128
#define Dc   512
#define Hc   8
#define DHc  64
#define NBc  6
#define MLPc 2048
#define Tc   512
#define BTc  (Bc*Tc)   // 8192

// ---------------- scratch (no allocations allowed) ----------------
__device__ float g_x[(size_t)BTc*Dc];        // residual stream  [B*T, D]
__device__ float g_h[(size_t)BTc*Dc];        // LN output        [B*T, D]
__device__ float g_q[(size_t)Bc*Hc*Tc*DHc];  // [B*H, T, DH]
__device__ float g_k[(size_t)Bc*Hc*Tc*DHc];
__device__ float g_v[(size_t)Bc*Hc*Tc*DHc];
__device__ float g_m1[(size_t)BTc*MLPc];     // MLP hidden [B*T, 4D]
__device__ float g_freq[Dc];                 // pos-emb denominators
__device__ float g_w1t[(size_t)NBc*MLPc*Dc]; // W1 transposed [NB][N=2048][K=512]
__device__ float g_w2t[(size_t)NBc*Dc*MLPc]; // W2 transposed [NB][N=512][K=2048]

// ---------------- mma.sync tf32 helpers (compute_103-safe PTX) -----
__device__ __forceinline__ uint32_t tf32u(float x) {   // round-to-nearest tf32
    uint32_t u; asm("cvt.rna.tf32.f32 %0, %1;" : "=r"(u) : "f"(x));
    return u;
}
__device__ __forceinline__ void mma_tf32(float* d, const uint32_t* a,
                                         const uint32_t* b) {
    asm volatile("mma.sync.aligned.m16n8k8.row.col.f32.tf32.tf32.f32 "
        "{%0,%1,%2,%3}, {%4,%5,%6,%7}, {%8,%9}, {%0,%1,%2,%3};"
        : "+f"(d[0]), "+f"(d[1]), "+f"(d[2]), "+f"(d[3])
        : "r"(a[0]), "r"(a[1]), "r"(a[2]), "r"(a[3]),
          "r"(b[0]), "r"(b[1]));
}

// ---------------- positional-embedding frequencies (fp64, tiny) ----
__global__ void pe_freq_kernel() {
    int d  = threadIdx.x;
    int je = d & ~1;
    g_freq[d] = (float)pow(10000.0, (double)je / 512.0);
}

// ---------------- embedding: x = src@embW + embb + PE; cls row -----
__global__ __launch_bounds__(128) void embed_kernel(
        const float* __restrict__ src, const float* __restrict__ Wemb,
        const float* __restrict__ bemb, const float* __restrict__ cls) {
    int row = blockIdx.x;               // 0..8191 = b*512 + t
    int b = row >> 9, t = row & 511;
    int tid = threadIdx.x;
    float* xo = g_x + (size_t)row * Dc;
    if (t == 0) {
        #pragma unroll
        for (int kk = 0; kk < 4; kk++) {
            int d = tid + 128*kk;
            xo[d] = cls[d] + ((d & 1) ? 1.0f : 0.0f);  // cos(0)=1, sin(0)=0
        }
        return;
    }
    __shared__ float ss[128];
    ss[tid] = src[((size_t)b*Sc + (t-1))*Fc + tid];
    __syncthreads();
    #pragma unroll
    for (int kk = 0; kk < 4; kk++) {
        int d = tid + 128*kk;
        float acc = bemb[d];
        #pragma unroll 8
        for (int f = 0; f < 128; f++) acc += ss[f] * Wemb[(size_t)f*Dc + d];
        float ang = (float)t / g_freq[d];
        acc += (d & 1) ? cosf(ang) : sinf(ang);
        xo[d] = acc;
    }
}

// ---------------- LayerNorm: g_h = LN(g_x)*g + b -------------------
__global__ __launch_bounds__(128) void ln_kernel(
        const float* __restrict__ gam, const float* __restrict__ bet) {
    int row = blockIdx.x, tid = threadIdx.x;
    const float4* xin = (const float4*)(g_x + (size_t)row*Dc);
    float4 v = xin[tid];
    float s  = v.x+v.y+v.z+v.w;
    float sq = v.x*v.x + v.y*v.y + v.z*v.z + v.w*v.w;
    #pragma unroll
    for (int o = 16; o; o >>= 1) {
        s  += __shfl_xor_sync(0xffffffffu, s,  o);
        sq += __shfl_xor_sync(0xffffffffu, sq, o);
    }
    __shared__ float sm[8];
    if ((tid & 31) == 0) { sm[tid>>5] = s; sm[4 + (tid>>5)] = sq; }
    __syncthreads();
    s  = sm[0]+sm[1]+sm[2]+sm[3];
    sq = sm[4]+sm[5]+sm[6]+sm[7];
    float mean = s * (1.f/512.f);
    float var  = sq * (1.f/512.f) - mean*mean;
    float rstd = rsqrtf(var + 1e-5f);
    float4 g4 = ((const float4*)gam)[tid];
    float4 b4 = ((const float4*)bet)[tid];
    float4 o;
    o.x = (v.x-mean)*rstd*g4.x + b4.x;
    o.y = (v.y-mean)*rstd*g4.y + b4.y;
    o.z = (v.z-mean)*rstd*g4.z + b4.z;
    o.w = (v.w-mean)*rstd*g4.w + b4.w;
    ((float4*)(g_h + (size_t)row*Dc))[tid] = o;
}

// ---------------- per-head QKV projection (64x64x64 tiles) ---------
__global__ __launch_bounds__(256) void qkv_kernel(
        const float* __restrict__ Wq, const float* __restrict__ bq,
        const float* __restrict__ Wk, const float* __restrict__ bk,
        const float* __restrict__ Wv, const float* __restrict__ bv) {
    __shared__ float Hs[64*65];   // input tile, padded (lane-varying reads)
    __shared__ float Ws[64*64];   // weights, unpadded (warp-uniform reads)
    int tid = threadIdx.x;
    int bh  = blockIdx.y; int b = bh >> 3, h = bh & 7;
    int t0  = blockIdx.x * 64;
    int z   = blockIdx.z;
    const float* W    = (z==0 ? Wq : (z==1 ? Wk : Wv)) + (size_t)h*4096;
    const float* bias = (z==0 ? bq : (z==1 ? bk : bv)) + h*64;
    float*       out  = (z==0 ? g_q : (z==1 ? g_k : g_v)) + (size_t)bh*Tc*64;

    for (int it = 0; it < 16; it++) {
        int idx = tid + 256*it; int rr = idx >> 6, cc = idx & 63;
        Hs[rr*65+cc] = g_h[((size_t)b*Tc + t0 + rr)*Dc + h*64 + cc];
        Ws[idx] = W[idx];
    }
    __syncthreads();
    int r = tid & 63, quad = tid >> 6;
    float acc[16];
    #pragma unroll
    for (int j = 0; j < 16; j++) acc[j] = bias[quad*16 + j];
    for (int d = 0; d < 64; d++) {
        float hv = Hs[r*65 + d];
        #pragma unroll
        for (int j4 = 0; j4 < 16; j4 += 4) {
            float4 wv = *(const float4*)&Ws[d*64 + quad*16 + j4];
            acc[j4+0] += hv*wv.x; acc[j4+1] += hv*wv.y;
            acc[j4+2] += hv*wv.z; acc[j4+3] += hv*wv.w;
        }
    }
    __syncthreads();
    #pragma unroll
    for (int j = 0; j < 16; j++) Hs[r*65 + quad*16 + j] = acc[j];
    __syncthreads();
    for (int it = 0; it < 16; it++) {
        int idx = tid + 256*it; int rr = idx >> 6, cc = idx & 63;
        out[(size_t)(t0+rr)*64 + cc] = Hs[rr*65+cc];
    }
}

// ---------------- flash attention + residual add -------------------
__global__ __launch_bounds__(256) void attn_kernel() {
    __shared__ float Qs[64*65];
    __shared__ float Ks[32*64];
    __shared__ float Vs[32*64];
    __shared__ float Ps[64*33];
    __shared__ float redM[64*4];
    __shared__ float redS[64*4];
    int tid = threadIdx.x;
    int bh  = blockIdx.y; int q0 = blockIdx.x * 64;
    const float* qb = g_q + (size_t)bh*Tc*64;
    const float* kb = g_k + (size_t)bh*Tc*64;
    const float* vb = g_v + (size_t)bh*Tc*64;

    for (int it = 0; it < 16; it++) {
        int idx = tid + 256*it; int rr = idx >> 6, cc = idx & 63;
        Qs[rr*65+cc] = qb[(size_t)(q0+rr)*64 + cc];
    }
    int r = tid & 63, quad = tid >> 6;
    float m_old = -1e30f, l_old = 0.f;
    float acc[16];
    #pragma unroll
    for (int j = 0; j < 16; j++) acc[j] = 0.f;

    for (int kt = 0; kt < 16; kt++) {
        __syncthreads();
        int k0 = kt * 32;
        for (int it = 0; it < 8; it++) {
            int idx = tid + 256*it; int rr = idx >> 6, cc = idx & 63;
            Ks[idx] = kb[(size_t)(k0+rr)*64 + cc];
            Vs[idx] = vb[(size_t)(k0+rr)*64 + cc];
        }
        __syncthreads();
        float s[8];
        #pragma unroll
        for (int j = 0; j < 8; j++) s[j] = 0.f;
        #pragma unroll
        for (int e4 = 0; e4 < 64; e4 += 4) {
            float q0v = Qs[r*65+e4+0], q1v = Qs[r*65+e4+1];
            float q2v = Qs[r*65+e4+2], q3v = Qs[r*65+e4+3];
            #pragma unroll
            for (int j = 0; j < 8; j++) {
                float4 kv = *(const float4*)&Ks[(quad*8+j)*64 + e4];
                s[j] += q0v*kv.x + q1v*kv.y + q2v*kv.z + q3v*kv.w;
            }
        }
        float lm = -1e30f;
        #pragma unroll
        for (int j = 0; j < 8; j++) { s[j] *= 0.125f; lm = fmaxf(lm, s[j]); }
        redM[r*4+quad] = lm;
        __syncthreads();
        float m_new = fmaxf(m_old,
            fmaxf(fmaxf(redM[r*4+0], redM[r*4+1]),
                  fmaxf(redM[r*4+2], redM[r*4+3])));
        float alpha = __expf(m_old - m_new);
        float lsum = 0.f;
        #pragma unroll
        for (int j = 0; j < 8; j++) {
            float p = __expf(s[j] - m_new);
            Ps[r*33 + quad*8 + j] = p;
            lsum += p;
        }
        redS[r*4+quad] = lsum;
        #pragma unroll
        for (int j = 0; j < 16; j++) acc[j] *= alpha;
        __syncthreads();
        l_old = l_old*alpha + (redS[r*4+0]+redS[r*4+1]+redS[r*4+2]+redS[r*4+3]);
        m_old = m_new;
        #pragma unroll 4
        for (int kc = 0; kc < 32; kc++) {
            float p = Ps[r*33 + kc];
            #pragma unroll
            for (int j4 = 0; j4 < 16; j4 += 4) {
                float4 vv = *(const float4*)&Vs[kc*64 + quad*16 + j4];
                acc[j4+0] += p*vv.x; acc[j4+1] += p*vv.y;
                acc[j4+2] += p*vv.z; acc[j4+3] += p*vv.w;
            }
        }
    }
    __syncthreads();
    float inv = 1.f / l_old;
    #pragma unroll
    for (int j = 0; j < 16; j++) Qs[r*65 + quad*16 + j] = acc[j] * inv;
    __syncthreads();
    int b = bh >> 3, h = bh & 7;
    float* xb = g_x + ((size_t)(b*Tc + q0))*Dc + h*64;
    for (int it = 0; it < 16; it++) {
        int idx = tid + 256*it; int rr = idx >> 6, cc = idx & 63;
        xb[(size_t)rr*Dc + cc] += Qs[rr*65+cc];
    }
}

// ---------------- weight transpose [K][N] -> [N][K] ----------------
__global__ __launch_bounds__(256) void transpose_kernel(
        const float* __restrict__ W, float* __restrict__ Wt, int K, int N) {
    __shared__ float t[32][33];
    int k0 = blockIdx.y * 32, n0 = blockIdx.x * 32;
    const float* Wb  = W  + (size_t)blockIdx.z * K * N;
    float*       Wtb = Wt + (size_t)blockIdx.z * K * N;
    int x = threadIdx.x, y = threadIdx.y;       // block (32, 8)
    #pragma unroll
    for (int i = 0; i < 32; i += 8)
        t[y+i][x] = Wb[(size_t)(k0+y+i)*N + n0 + x];
    __syncthreads();
    #pragma unroll
    for (int i = 0; i < 32; i += 8)
        Wtb[(size_t)(n0+y+i)*K + k0 + x] = t[x][y+i];
}

// ---------------- tf32 mma.sync GEMM, 128x128 tile -----------------
__device__ __forceinline__ float geluf(float x) {
    return 0.5f * x * (1.0f + erff(x * 0.70710678118654752f));
}

// MODE 0: C = gelu(A@Bt^T + bias)    (FC1)
// MODE 1: C += A@Bt^T + bias         (FC2, residual)
// A: [M,K] row-major; Bt: [N,K] row-major (K-major); K % 32 == 0.
// 128 threads = 4 warps (2x2), warp tile 64x64 = 4x8 m16n8k8 fragments.
// Smem stride 36 words -> conflict-free fragment loads
// (bank = (4*(lane>>2) + (lane&3)) % 32 is a bijection over the warp).
template<int MODE>
__global__ __launch_bounds__(128) void tc_gemm(
        const float* __restrict__ A, const float* __restrict__ Bt,
        const float* __restrict__ bias, float* __restrict__ C,
        int N, int K) {
    __shared__ uint32_t As[128*36];   // 18KB, tf32-encoded
    __shared__ uint32_t Bs[128*36];   // 18KB
    int tid = threadIdx.x;
    int wid = tid >> 5, lane = tid & 31;
    int wm = wid & 1, wn = wid >> 1;          // 2x2 warps
    int m0 = blockIdx.y * 128, n0 = blockIdx.x * 128;
    int lr = lane >> 2, lc = lane & 3;        // fragment row / k within quad

    float acc[4][8][4];
    #pragma unroll
    for (int mt = 0; mt < 4; mt++)
        #pragma unroll
        for (int nt = 0; nt < 8; nt++)
            #pragma unroll
            for (int j = 0; j < 4; j++) acc[mt][nt][j] = 0.f;

    const float* Ab = A  + (size_t)m0 * K;
    const float* Bb = Bt + (size_t)n0 * K;
    int nslab = K >> 5;

    for (int s = 0; s < nslab; s++) {
        // -------- stage: gmem -> regs (latency outside the sync) ----
        float4 ar[8], br[8];
        #pragma unroll
        for (int i = 0; i < 8; i++) {
            int idx = tid + 128*i;
            int row = idx >> 3, c4 = idx & 7;
            ar[i] = *(const float4*)(Ab + (size_t)row*K + s*32 + c4*4);
            br[i] = *(const float4*)(Bb + (size_t)row*K + s*32 + c4*4);
        }
        __syncthreads();                       // prior slab fully consumed
        #pragma unroll
        for (int i = 0; i < 8; i++) {
            int idx = tid + 128*i;
            int row = idx >> 3, c4 = idx & 7;
            uint4 av = { tf32u(ar[i].x), tf32u(ar[i].y),
                         tf32u(ar[i].z), tf32u(ar[i].w) };
            uint4 bv = { tf32u(br[i].x), tf32u(br[i].y),
                         tf32u(br[i].z), tf32u(br[i].w) };
            *(uint4*)&As[row*36 + c4*4] = av;
            *(uint4*)&Bs[row*36 + c4*4] = bv;
        }
        __syncthreads();

        // -------- compute: 4 k8-steps x 32 MMAs per warp ------------
        #pragma unroll
        for (int ks = 0; ks < 4; ks++) {
            int kb = ks*8 + lc;
            uint32_t af[4][4];
            #pragma unroll
            for (int mt = 0; mt < 4; mt++) {
                int r0 = wm*64 + mt*16 + lr;
                af[mt][0] = As[r0*36 + kb];
                af[mt][1] = As[(r0+8)*36 + kb];
                af[mt][2] = As[r0*36 + kb + 4];
                af[mt][3] = As[(r0+8)*36 + kb + 4];
            }
            #pragma unroll
            for (int nt = 0; nt < 8; nt++) {
                int nr = wn*64 + nt*8 + lr;
                uint32_t bf[2];
                bf[0] = Bs[nr*36 + kb];
                bf[1] = Bs[nr*36 + kb + 4];
                #pragma unroll
                for (int mt = 0; mt < 4; mt++)
                    mma_tf32(acc[mt][nt], af[mt], bf);
            }
        }
    }

    // -------- epilogue: bias + gelu / residual, float2 stores -------
    #pragma unroll
    for (int mt = 0; mt < 4; mt++) {
        int row = m0 + wm*64 + mt*16 + lr;
        #pragma unroll
        for (int nt = 0; nt < 8; nt++) {
            int col = n0 + wn*64 + nt*8 + lc*2;
            float b0v = bias[col], b1v = bias[col+1];
            float* p0 = C + (size_t)row*N + col;
            float* p1 = C + (size_t)(row+8)*N + col;
            float v0 = acc[mt][nt][0] + b0v, v1 = acc[mt][nt][1] + b1v;
            float v2 = acc[mt][nt][2] + b0v, v3 = acc[mt][nt][3] + b1v;
            if (MODE == 0) {
                v0 = geluf(v0); v1 = geluf(v1); v2 = geluf(v2); v3 = geluf(v3);
            } else {
                float2 o0 = *(const float2*)p0;
                float2 o1 = *(const float2*)p1;
                v0 += o0.x; v1 += o0.y; v2 += o1.x; v3 += o1.y;
            }
            float2 r0 = {v0, v1}, r1 = {v2, v3};
            *(float2*)p0 = r0;
            *(float2*)p1 = r1;
        }
    }
}

// ---------------- classifier head ---------------------------------
__global__ __launch_bounds__(512) void head_kernel(
        const float* __restrict__ hW, const float* __restrict__ hb,
        float* __restrict__ out) {
    int w = threadIdx.x >> 5, lane = threadIdx.x & 31;
    const float* xr = g_x + (size_t)w * Tc * Dc;
    float s = 0.f;
    for (int d = lane; d < Dc; d += 32) s += xr[d] * hW[d];
    #pragma unroll
    for (int o = 16; o; o >>= 1) s += __shfl_xor_sync(0xffffffffu, s, o);
    if (lane == 0) out[w] = 1.f / (1.f + expf(-(s + hb[0])));
}

// ---------------- launcher -----------------------------------------
extern "C" void kernel_launch(void* const* d_in, const int* in_sizes, int n_in,
                              void* d_out, int out_size) {
    const float* src  = (const float*)d_in[0];
    const float* embW = (const float*)d_in[1];
    const float* embb = (const float*)d_in[2];
    const float* cls  = (const float*)d_in[3];
    const float* ln1g = (const float*)d_in[4];
    const float* ln1b = (const float*)d_in[5];
    const float* Wq   = (const float*)d_in[6];
    const float* bq   = (const float*)d_in[7];
    const float* Wk   = (const float*)d_in[8];
    const float* bk   = (const float*)d_in[9];
    const float* Wv   = (const float*)d_in[10];
    const float* bv   = (const float*)d_in[11];
    const float* ln2g = (const float*)d_in[12];
    const float* ln2b = (const float*)d_in[13];
    const float* W1   = (const float*)d_in[14];
    const float* b1   = (const float*)d_in[15];
    const float* W2   = (const float*)d_in[16];
    const float* b2   = (const float*)d_in[17];
    const float* hW   = (const float*)d_in[18];
    const float* hb   = (const float*)d_in[19];
    float* out = (float*)d_out;

    float *ph, *pm1, *px, *pw1t, *pw2t;
    cudaGetSymbolAddress((void**)&ph,   g_h);
    cudaGetSymbolAddress((void**)&pm1,  g_m1);
    cudaGetSymbolAddress((void**)&px,   g_x);
    cudaGetSymbolAddress((void**)&pw1t, g_w1t);
    cudaGetSymbolAddress((void**)&pw2t, g_w2t);

    pe_freq_kernel<<<1, 512>>>();
    // pre-transpose weights to [N][K] K-major (all 6 blocks)
    transpose_kernel<<<dim3(MLPc/32, Dc/32, NBc), dim3(32,8)>>>(W1, pw1t, Dc, MLPc);
    transpose_kernel<<<dim3(Dc/32, MLPc/32, NBc), dim3(32,8)>>>(W2, pw2t, MLPc, Dc);
    embed_kernel<<<BTc, 128>>>(src, embW, embb, cls);
    for (int i = 0; i < NBc; i++) {
        ln_kernel<<<BTc, 128>>>(ln1g + i*Dc, ln1b + i*Dc);
        qkv_kernel<<<dim3(Tc/64, Bc*Hc, 3), 256>>>(
            Wq + (size_t)i*Hc*DHc*DHc, bq + (size_t)i*Hc*DHc,
            Wk + (size_t)i*Hc*DHc*DHc, bk + (size_t)i*Hc*DHc,
            Wv + (size_t)i*Hc*DHc*DHc, bv + (size_t)i*Hc*DHc);
        attn_kernel<<<dim3(Tc/64, Bc*Hc), 256>>>();
        ln_kernel<<<BTc, 128>>>(ln2g + i*Dc, ln2b + i*Dc);
        tc_gemm<0><<<dim3(MLPc/128, BTc/128), 128>>>(
            ph, pw1t + (size_t)i*MLPc*Dc, b1 + (size_t)i*MLPc, pm1, MLPc, Dc);
        tc_gemm<1><<<dim3(Dc/128, BTc/128), 128>>>(
            pm1, pw2t + (size_t)i*Dc*MLPc, b2 + (size_t)i*Dc, px, Dc, MLPc);
    }
    head_kernel<<<1, 512>>>(hW, hb, out);
}

// round 15
// speedup vs baseline: 2.6806x; 1.5141x over previous
#include <cuda_runtime.h>
#include <math.h>
#include <stdint.h>

// Problem dims
#define Bc   16
#define Sc   511
#define Fc   128
#define Dc   512
#define Hc   8
#define DHc  64
#define NBc  6
#define MLPc 2048
#define Tc   512
#define BTc  (Bc*Tc)   // 8192

// ---------------- scratch (no allocations allowed) ----------------
__device__ float g_x[(size_t)BTc*Dc];        // residual stream  [B*T, D]
__device__ float g_h[(size_t)BTc*Dc];        // LN output        [B*T, D]
__device__ float g_q[(size_t)Bc*Hc*Tc*DHc];  // [B*H, T, DH]
__device__ float g_k[(size_t)Bc*Hc*Tc*DHc];  // [B*H, T, DH]
__device__ float g_v[(size_t)Bc*Hc*Tc*DHc];  // [B*H, DH, T]  (TRANSPOSED)
__device__ float g_m1[(size_t)BTc*MLPc];     // MLP hidden [B*T, 4D]
__device__ float g_freq[Dc];                 // pos-emb denominators
__device__ float g_w1t[(size_t)NBc*MLPc*Dc]; // W1 transposed [NB][N=2048][K=512]
__device__ float g_w2t[(size_t)NBc*Dc*MLPc]; // W2 transposed [NB][N=512][K=2048]

// ---------------- mma.sync tf32 helpers (compute_103-safe PTX) -----
__device__ __forceinline__ uint32_t tf32u(float x) {   // round-to-nearest tf32
    uint32_t u; asm("cvt.rna.tf32.f32 %0, %1;" : "=r"(u) : "f"(x));
    return u;
}
__device__ __forceinline__ void mma_tf32(float* d, const uint32_t* a,
                                         const uint32_t* b) {
    asm volatile("mma.sync.aligned.m16n8k8.row.col.f32.tf32.tf32.f32 "
        "{%0,%1,%2,%3}, {%4,%5,%6,%7}, {%8,%9}, {%0,%1,%2,%3};"
        : "+f"(d[0]), "+f"(d[1]), "+f"(d[2]), "+f"(d[3])
        : "r"(a[0]), "r"(a[1]), "r"(a[2]), "r"(a[3]),
          "r"(b[0]), "r"(b[1]));
}

// ---------------- positional-embedding frequencies (fp64, tiny) ----
__global__ void pe_freq_kernel() {
    int d  = threadIdx.x;
    int je = d & ~1;
    g_freq[d] = (float)pow(10000.0, (double)je / 512.0);
}

// ---------------- embedding: x = src@embW + embb + PE; cls row -----
__global__ __launch_bounds__(128) void embed_kernel(
        const float* __restrict__ src, const float* __restrict__ Wemb,
        const float* __restrict__ bemb, const float* __restrict__ cls) {
    int row = blockIdx.x;               // 0..8191 = b*512 + t
    int b = row >> 9, t = row & 511;
    int tid = threadIdx.x;
    float* xo = g_x + (size_t)row * Dc;
    if (t == 0) {
        #pragma unroll
        for (int kk = 0; kk < 4; kk++) {
            int d = tid + 128*kk;
            xo[d] = cls[d] + ((d & 1) ? 1.0f : 0.0f);  // cos(0)=1, sin(0)=0
        }
        return;
    }
    __shared__ float ss[128];
    ss[tid] = src[((size_t)b*Sc + (t-1))*Fc + tid];
    __syncthreads();
    #pragma unroll
    for (int kk = 0; kk < 4; kk++) {
        int d = tid + 128*kk;
        float acc = bemb[d];
        #pragma unroll 8
        for (int f = 0; f < 128; f++) acc += ss[f] * Wemb[(size_t)f*Dc + d];
        float ang = (float)t / g_freq[d];
        acc += (d & 1) ? cosf(ang) : sinf(ang);
        xo[d] = acc;
    }
}

// ---------------- LayerNorm: g_h = LN(g_x)*g + b -------------------
__global__ __launch_bounds__(128) void ln_kernel(
        const float* __restrict__ gam, const float* __restrict__ bet) {
    int row = blockIdx.x, tid = threadIdx.x;
    const float4* xin = (const float4*)(g_x + (size_t)row*Dc);
    float4 v = xin[tid];
    float s  = v.x+v.y+v.z+v.w;
    float sq = v.x*v.x + v.y*v.y + v.z*v.z + v.w*v.w;
    #pragma unroll
    for (int o = 16; o; o >>= 1) {
        s  += __shfl_xor_sync(0xffffffffu, s,  o);
        sq += __shfl_xor_sync(0xffffffffu, sq, o);
    }
    __shared__ float sm[8];
    if ((tid & 31) == 0) { sm[tid>>5] = s; sm[4 + (tid>>5)] = sq; }
    __syncthreads();
    s  = sm[0]+sm[1]+sm[2]+sm[3];
    sq = sm[4]+sm[5]+sm[6]+sm[7];
    float mean = s * (1.f/512.f);
    float var  = sq * (1.f/512.f) - mean*mean;
    float rstd = rsqrtf(var + 1e-5f);
    float4 g4 = ((const float4*)gam)[tid];
    float4 b4 = ((const float4*)bet)[tid];
    float4 o;
    o.x = (v.x-mean)*rstd*g4.x + b4.x;
    o.y = (v.y-mean)*rstd*g4.y + b4.y;
    o.z = (v.z-mean)*rstd*g4.z + b4.z;
    o.w = (v.w-mean)*rstd*g4.w + b4.w;
    ((float4*)(g_h + (size_t)row*Dc))[tid] = o;
}

// ---------------- per-head QKV projection (64x64x64 tiles) ---------
// V is written TRANSPOSED: g_v[bh][dh][t]
__global__ __launch_bounds__(256) void qkv_kernel(
        const float* __restrict__ Wq, const float* __restrict__ bq,
        const float* __restrict__ Wk, const float* __restrict__ bk,
        const float* __restrict__ Wv, const float* __restrict__ bv) {
    __shared__ float Hs[64*65];   // input tile, padded (lane-varying reads)
    __shared__ float Ws[64*64];   // weights, unpadded (warp-uniform reads)
    int tid = threadIdx.x;
    int bh  = blockIdx.y; int b = bh >> 3, h = bh & 7;
    int t0  = blockIdx.x * 64;
    int z   = blockIdx.z;
    const float* W    = (z==0 ? Wq : (z==1 ? Wk : Wv)) + (size_t)h*4096;
    const float* bias = (z==0 ? bq : (z==1 ? bk : bv)) + h*64;
    float*       out  = (z==0 ? g_q : (z==1 ? g_k : g_v)) + (size_t)bh*Tc*64;

    for (int it = 0; it < 16; it++) {
        int idx = tid + 256*it; int rr = idx >> 6, cc = idx & 63;
        Hs[rr*65+cc] = g_h[((size_t)b*Tc + t0 + rr)*Dc + h*64 + cc];
        Ws[idx] = W[idx];
    }
    __syncthreads();
    int r = tid & 63, quad = tid >> 6;
    float acc[16];
    #pragma unroll
    for (int j = 0; j < 16; j++) acc[j] = bias[quad*16 + j];
    for (int d = 0; d < 64; d++) {
        float hv = Hs[r*65 + d];
        #pragma unroll
        for (int j4 = 0; j4 < 16; j4 += 4) {
            float4 wv = *(const float4*)&Ws[d*64 + quad*16 + j4];
            acc[j4+0] += hv*wv.x; acc[j4+1] += hv*wv.y;
            acc[j4+2] += hv*wv.z; acc[j4+3] += hv*wv.w;
        }
    }
    __syncthreads();
    #pragma unroll
    for (int j = 0; j < 16; j++) Hs[r*65 + quad*16 + j] = acc[j];
    __syncthreads();
    if (z == 2) {
        // transposed write: out[dh][t]
        for (int it = 0; it < 16; it++) {
            int idx = tid + 256*it; int tt = idx & 63, dd = idx >> 6;
            out[(size_t)dd*Tc + t0 + tt] = Hs[tt*65 + dd];
        }
    } else {
        for (int it = 0; it < 16; it++) {
            int idx = tid + 256*it; int rr = idx >> 6, cc = idx & 63;
            out[(size_t)(t0+rr)*64 + cc] = Hs[rr*65+cc];
        }
    }
}

// ---------------- tensor-core flash attention + residual -----------
// 64 queries/CTA, 4 warps (16 q each), 32-key tiles, tf32 mma.sync.
__global__ __launch_bounds__(128) void attn_tc_kernel() {
    __shared__ uint32_t Qs[64*68];      // Q tile, tf32  (17.4KB)
    __shared__ uint32_t Ks[32*68];      // K tile, tf32  ( 8.7KB)
    __shared__ uint32_t Vs[64*36];      // V^T tile, tf32 (9.2KB)
    __shared__ uint32_t Ps[4][16*36];   // per-warp P, tf32 (9.2KB)
    int tid = threadIdx.x, wid = tid >> 5, lane = tid & 31;
    int lr = lane >> 2, lc = lane & 3;
    int bh = blockIdx.y; int q0 = blockIdx.x * 64;
    const float* qb  = g_q + ((size_t)bh*Tc + q0)*64;
    const float* kbp = g_k + (size_t)bh*Tc*64;
    const float* vtb = g_v + (size_t)bh*64*Tc;   // [dh][t]

    // stage Q (64x64) -> tf32
    #pragma unroll
    for (int i = 0; i < 8; i++) {
        int idx = tid + 128*i;              // 1024 float4
        int row = idx >> 4, c4 = idx & 15;
        float4 v = *(const float4*)(qb + (size_t)row*64 + c4*4);
        uint4 u = {tf32u(v.x), tf32u(v.y), tf32u(v.z), tf32u(v.w)};
        *(uint4*)&Qs[row*68 + c4*4] = u;
    }

    float m0 = -1e30f, m1 = -1e30f, l0 = 0.f, l1 = 0.f;
    float of[8][4];
    #pragma unroll
    for (int nf = 0; nf < 8; nf++)
        #pragma unroll
        for (int j = 0; j < 4; j++) of[nf][j] = 0.f;
    int r0 = wid*16 + lr;                   // local query row (a-frag row)

    for (int kt = 0; kt < 16; kt++) {
        int k0 = kt * 32;
        // prefetch K/V tile to regs
        float4 kr[4], vr[4];
        #pragma unroll
        for (int i = 0; i < 4; i++) {
            int idx = tid + 128*i;          // 512 float4 each
            int row = idx >> 4, c4 = idx & 15;
            kr[i] = *(const float4*)(kbp + (size_t)(k0+row)*64 + c4*4);
            int rv = idx >> 3, cv = idx & 7;
            vr[i] = *(const float4*)(vtb + (size_t)rv*Tc + k0 + cv*4);
        }
        __syncthreads();                     // prior tile fully consumed
        #pragma unroll
        for (int i = 0; i < 4; i++) {
            int idx = tid + 128*i;
            int row = idx >> 4, c4 = idx & 15;
            uint4 ku = {tf32u(kr[i].x), tf32u(kr[i].y), tf32u(kr[i].z), tf32u(kr[i].w)};
            *(uint4*)&Ks[row*68 + c4*4] = ku;
            int rv = idx >> 3, cv = idx & 7;
            uint4 vu = {tf32u(vr[i].x), tf32u(vr[i].y), tf32u(vr[i].z), tf32u(vr[i].w)};
            *(uint4*)&Vs[rv*36 + cv*4] = vu;
        }
        __syncthreads();

        // ---- S = Q K^T  (warp: 16 q x 32 keys) ----
        float sf[4][4];
        #pragma unroll
        for (int nf = 0; nf < 4; nf++)
            #pragma unroll
            for (int j = 0; j < 4; j++) sf[nf][j] = 0.f;
        #pragma unroll
        for (int ks = 0; ks < 8; ks++) {
            int kb2 = ks*8 + lc;
            uint32_t qf[4];
            qf[0] = Qs[r0*68 + kb2];
            qf[1] = Qs[(r0+8)*68 + kb2];
            qf[2] = Qs[r0*68 + kb2 + 4];
            qf[3] = Qs[(r0+8)*68 + kb2 + 4];
            #pragma unroll
            for (int nf = 0; nf < 4; nf++) {
                uint32_t bf[2];
                bf[0] = Ks[(nf*8+lr)*68 + kb2];
                bf[1] = Ks[(nf*8+lr)*68 + kb2 + 4];
                mma_tf32(sf[nf], qf, bf);
            }
        }

        // ---- online softmax in fragment layout ----
        float tm0 = -1e30f, tm1 = -1e30f;
        #pragma unroll
        for (int nf = 0; nf < 4; nf++) {
            sf[nf][0] *= 0.125f; sf[nf][1] *= 0.125f;
            sf[nf][2] *= 0.125f; sf[nf][3] *= 0.125f;
            tm0 = fmaxf(tm0, fmaxf(sf[nf][0], sf[nf][1]));
            tm1 = fmaxf(tm1, fmaxf(sf[nf][2], sf[nf][3]));
        }
        tm0 = fmaxf(tm0, __shfl_xor_sync(0xffffffffu, tm0, 1));
        tm0 = fmaxf(tm0, __shfl_xor_sync(0xffffffffu, tm0, 2));
        tm1 = fmaxf(tm1, __shfl_xor_sync(0xffffffffu, tm1, 1));
        tm1 = fmaxf(tm1, __shfl_xor_sync(0xffffffffu, tm1, 2));
        float mn0 = fmaxf(m0, tm0), mn1 = fmaxf(m1, tm1);
        float a0 = __expf(m0 - mn0), a1 = __expf(m1 - mn1);
        float rs0 = 0.f, rs1 = 0.f;
        #pragma unroll
        for (int nf = 0; nf < 4; nf++) {
            float p00 = __expf(sf[nf][0] - mn0), p01 = __expf(sf[nf][1] - mn0);
            float p10 = __expf(sf[nf][2] - mn1), p11 = __expf(sf[nf][3] - mn1);
            rs0 += p00 + p01; rs1 += p10 + p11;
            uint2 w0 = {tf32u(p00), tf32u(p01)};
            uint2 w1 = {tf32u(p10), tf32u(p11)};
            *(uint2*)&Ps[wid][lr*36 + nf*8 + 2*lc] = w0;
            *(uint2*)&Ps[wid][(lr+8)*36 + nf*8 + 2*lc] = w1;
        }
        rs0 += __shfl_xor_sync(0xffffffffu, rs0, 1);
        rs0 += __shfl_xor_sync(0xffffffffu, rs0, 2);
        rs1 += __shfl_xor_sync(0xffffffffu, rs1, 1);
        rs1 += __shfl_xor_sync(0xffffffffu, rs1, 2);
        l0 = l0*a0 + rs0; l1 = l1*a1 + rs1;
        m0 = mn0; m1 = mn1;
        #pragma unroll
        for (int nf = 0; nf < 8; nf++) {
            of[nf][0] *= a0; of[nf][1] *= a0;
            of[nf][2] *= a1; of[nf][3] *= a1;
        }
        __syncwarp();                        // P writes -> P reads (same warp)

        // ---- O += P V  (warp: 16 q x 64 dh, k=32 keys) ----
        #pragma unroll
        for (int ks = 0; ks < 4; ks++) {
            int kb2 = ks*8 + lc;
            uint32_t af[4];
            af[0] = Ps[wid][lr*36 + kb2];
            af[1] = Ps[wid][(lr+8)*36 + kb2];
            af[2] = Ps[wid][lr*36 + kb2 + 4];
            af[3] = Ps[wid][(lr+8)*36 + kb2 + 4];
            #pragma unroll
            for (int nf = 0; nf < 8; nf++) {
                uint32_t bf[2];
                bf[0] = Vs[(nf*8+lr)*36 + kb2];
                bf[1] = Vs[(nf*8+lr)*36 + kb2 + 4];
                mma_tf32(of[nf], af, bf);
            }
        }
    }

    // ---- epilogue: normalize + residual add ----
    int b = bh >> 3, h = bh & 7;
    float inv0 = 1.f / l0, inv1 = 1.f / l1;
    int row0 = q0 + r0;
    float* x0 = g_x + ((size_t)(b*Tc) + row0)*Dc + h*64;
    float* x1 = x0 + (size_t)8*Dc;
    #pragma unroll
    for (int nf = 0; nf < 8; nf++) {
        int col = nf*8 + 2*lc;
        float2 o0 = *(float2*)(x0 + col);
        o0.x += of[nf][0]*inv0; o0.y += of[nf][1]*inv0;
        *(float2*)(x0 + col) = o0;
        float2 o1 = *(float2*)(x1 + col);
        o1.x += of[nf][2]*inv1; o1.y += of[nf][3]*inv1;
        *(float2*)(x1 + col) = o1;
    }
}

// ---------------- weight transpose [K][N] -> [N][K] ----------------
__global__ __launch_bounds__(256) void transpose_kernel(
        const float* __restrict__ W, float* __restrict__ Wt, int K, int N) {
    __shared__ float t[32][33];
    int k0 = blockIdx.y * 32, n0 = blockIdx.x * 32;
    const float* Wb  = W  + (size_t)blockIdx.z * K * N;
    float*       Wtb = Wt + (size_t)blockIdx.z * K * N;
    int x = threadIdx.x, y = threadIdx.y;       // block (32, 8)
    #pragma unroll
    for (int i = 0; i < 32; i += 8)
        t[y+i][x] = Wb[(size_t)(k0+y+i)*N + n0 + x];
    __syncthreads();
    #pragma unroll
    for (int i = 0; i < 32; i += 8)
        Wtb[(size_t)(n0+y+i)*K + k0 + x] = t[x][y+i];
}

// ---------------- tf32 mma.sync GEMM, 128x128 tile -----------------
__device__ __forceinline__ float geluf(float x) {
    return 0.5f * x * (1.0f + erff(x * 0.70710678118654752f));
}

// MODE 0: C = gelu(A@Bt^T + bias)    (FC1)
// MODE 1: C += A@Bt^T + bias         (FC2, residual)
template<int MODE>
__global__ __launch_bounds__(128) void tc_gemm(
        const float* __restrict__ A, const float* __restrict__ Bt,
        const float* __restrict__ bias, float* __restrict__ C,
        int N, int K) {
    __shared__ uint32_t As[128*36];   // 18KB, tf32-encoded
    __shared__ uint32_t Bs[128*36];   // 18KB
    int tid = threadIdx.x;
    int wid = tid >> 5, lane = tid & 31;
    int wm = wid & 1, wn = wid >> 1;          // 2x2 warps
    int m0 = blockIdx.y * 128, n0 = blockIdx.x * 128;
    int lr = lane >> 2, lc = lane & 3;

    float acc[4][8][4];
    #pragma unroll
    for (int mt = 0; mt < 4; mt++)
        #pragma unroll
        for (int nt = 0; nt < 8; nt++)
            #pragma unroll
            for (int j = 0; j < 4; j++) acc[mt][nt][j] = 0.f;

    const float* Ab = A  + (size_t)m0 * K;
    const float* Bb = Bt + (size_t)n0 * K;
    int nslab = K >> 5;

    for (int s = 0; s < nslab; s++) {
        float4 ar[8], br[8];
        #pragma unroll
        for (int i = 0; i < 8; i++) {
            int idx = tid + 128*i;
            int row = idx >> 3, c4 = idx & 7;
            ar[i] = *(const float4*)(Ab + (size_t)row*K + s*32 + c4*4);
            br[i] = *(const float4*)(Bb + (size_t)row*K + s*32 + c4*4);
        }
        __syncthreads();
        #pragma unroll
        for (int i = 0; i < 8; i++) {
            int idx = tid + 128*i;
            int row = idx >> 3, c4 = idx & 7;
            uint4 av = { tf32u(ar[i].x), tf32u(ar[i].y),
                         tf32u(ar[i].z), tf32u(ar[i].w) };
            uint4 bv = { tf32u(br[i].x), tf32u(br[i].y),
                         tf32u(br[i].z), tf32u(br[i].w) };
            *(uint4*)&As[row*36 + c4*4] = av;
            *(uint4*)&Bs[row*36 + c4*4] = bv;
        }
        __syncthreads();

        #pragma unroll
        for (int ks = 0; ks < 4; ks++) {
            int kb = ks*8 + lc;
            uint32_t af[4][4];
            #pragma unroll
            for (int mt = 0; mt < 4; mt++) {
                int r0 = wm*64 + mt*16 + lr;
                af[mt][0] = As[r0*36 + kb];
                af[mt][1] = As[(r0+8)*36 + kb];
                af[mt][2] = As[r0*36 + kb + 4];
                af[mt][3] = As[(r0+8)*36 + kb + 4];
            }
            #pragma unroll
            for (int nt = 0; nt < 8; nt++) {
                int nr = wn*64 + nt*8 + lr;
                uint32_t bf[2];
                bf[0] = Bs[nr*36 + kb];
                bf[1] = Bs[nr*36 + kb + 4];
                #pragma unroll
                for (int mt = 0; mt < 4; mt++)
                    mma_tf32(acc[mt][nt], af[mt], bf);
            }
        }
    }

    #pragma unroll
    for (int mt = 0; mt < 4; mt++) {
        int row = m0 + wm*64 + mt*16 + lr;
        #pragma unroll
        for (int nt = 0; nt < 8; nt++) {
            int col = n0 + wn*64 + nt*8 + lc*2;
            float b0v = bias[col], b1v = bias[col+1];
            float* p0 = C + (size_t)row*N + col;
            float* p1 = C + (size_t)(row+8)*N + col;
            float v0 = acc[mt][nt][0] + b0v, v1 = acc[mt][nt][1] + b1v;
            float v2 = acc[mt][nt][2] + b0v, v3 = acc[mt][nt][3] + b1v;
            if (MODE == 0) {
                v0 = geluf(v0); v1 = geluf(v1); v2 = geluf(v2); v3 = geluf(v3);
            } else {
                float2 o0 = *(const float2*)p0;
                float2 o1 = *(const float2*)p1;
                v0 += o0.x; v1 += o0.y; v2 += o1.x; v3 += o1.y;
            }
            float2 r0 = {v0, v1}, r1 = {v2, v3};
            *(float2*)p0 = r0;
            *(float2*)p1 = r1;
        }
    }
}

// ---------------- classifier head ---------------------------------
__global__ __launch_bounds__(512) void head_kernel(
        const float* __restrict__ hW, const float* __restrict__ hb,
        float* __restrict__ out) {
    int w = threadIdx.x >> 5, lane = threadIdx.x & 31;
    const float* xr = g_x + (size_t)w * Tc * Dc;
    float s = 0.f;
    for (int d = lane; d < Dc; d += 32) s += xr[d] * hW[d];
    #pragma unroll
    for (int o = 16; o; o >>= 1) s += __shfl_xor_sync(0xffffffffu, s, o);
    if (lane == 0) out[w] = 1.f / (1.f + expf(-(s + hb[0])));
}

// ---------------- launcher -----------------------------------------
extern "C" void kernel_launch(void* const* d_in, const int* in_sizes, int n_in,
                              void* d_out, int out_size) {
    const float* src  = (const float*)d_in[0];
    const float* embW = (const float*)d_in[1];
    const float* embb = (const float*)d_in[2];
    const float* cls  = (const float*)d_in[3];
    const float* ln1g = (const float*)d_in[4];
    const float* ln1b = (const float*)d_in[5];
    const float* Wq   = (const float*)d_in[6];
    const float* bq   = (const float*)d_in[7];
    const float* Wk   = (const float*)d_in[8];
    const float* bk   = (const float*)d_in[9];
    const float* Wv   = (const float*)d_in[10];
    const float* bv   = (const float*)d_in[11];
    const float* ln2g = (const float*)d_in[12];
    const float* ln2b = (const float*)d_in[13];
    const float* W1   = (const float*)d_in[14];
    const float* b1   = (const float*)d_in[15];
    const float* W2   = (const float*)d_in[16];
    const float* b2   = (const float*)d_in[17];
    const float* hW   = (const float*)d_in[18];
    const float* hb   = (const float*)d_in[19];
    float* out = (float*)d_out;

    float *ph, *pm1, *px, *pw1t, *pw2t;
    cudaGetSymbolAddress((void**)&ph,   g_h);
    cudaGetSymbolAddress((void**)&pm1,  g_m1);
    cudaGetSymbolAddress((void**)&px,   g_x);
    cudaGetSymbolAddress((void**)&pw1t, g_w1t);
    cudaGetSymbolAddress((void**)&pw2t, g_w2t);

    pe_freq_kernel<<<1, 512>>>();
    transpose_kernel<<<dim3(MLPc/32, Dc/32, NBc), dim3(32,8)>>>(W1, pw1t, Dc, MLPc);
    transpose_kernel<<<dim3(Dc/32, MLPc/32, NBc), dim3(32,8)>>>(W2, pw2t, MLPc, Dc);
    embed_kernel<<<BTc, 128>>>(src, embW, embb, cls);
    for (int i = 0; i < NBc; i++) {
        ln_kernel<<<BTc, 128>>>(ln1g + i*Dc, ln1b + i*Dc);
        qkv_kernel<<<dim3(Tc/64, Bc*Hc, 3), 256>>>(
            Wq + (size_t)i*Hc*DHc*DHc, bq + (size_t)i*Hc*DHc,
            Wk + (size_t)i*Hc*DHc*DHc, bk + (size_t)i*Hc*DHc,
            Wv + (size_t)i*Hc*DHc*DHc, bv + (size_t)i*Hc*DHc);
        attn_tc_kernel<<<dim3(Tc/64, Bc*Hc), 128>>>();
        ln_kernel<<<BTc, 128>>>(ln2g + i*Dc, ln2b + i*Dc);
        tc_gemm<0><<<dim3(MLPc/128, BTc/128), 128>>>(
            ph, pw1t + (size_t)i*MLPc*Dc, b1 + (size_t)i*MLPc, pm1, MLPc, Dc);
        tc_gemm<1><<<dim3(Dc/128, BTc/128), 128>>>(
            pm1, pw2t + (size_t)i*Dc*MLPc, b2 + (size_t)i*Dc, px, Dc, MLPc);
    }
    head_kernel<<<1, 512>>>(hW, hb, out);
}

// round 16
// speedup vs baseline: 4.0366x; 1.5059x over previous
#include <cuda_runtime.h>
#include <math.h>
#include <stdint.h>

// Problem dims
#define Bc   16
#define Sc   511
#define Fc   128
#define Dc   512
#define Hc   8
#define DHc  64
#define NBc  6
#define MLPc 2048
#define Tc   512
#define BTc  (Bc*Tc)   // 8192

// ---------------- scratch (no allocations allowed) ----------------
__device__ float g_x[(size_t)BTc*Dc];        // residual stream  [B*T, D]
__device__ float g_h[(size_t)BTc*Dc];        // LN output        [B*T, D]
__device__ float g_q[(size_t)Bc*Hc*Tc*DHc];  // [B*H, T, DH]
__device__ float g_k[(size_t)Bc*Hc*Tc*DHc];  // [B*H, T, DH]
__device__ float g_v[(size_t)Bc*Hc*Tc*DHc];  // [B*H, DH, T]  (TRANSPOSED)
__device__ float g_m1[(size_t)BTc*MLPc];     // MLP hidden [B*T, 4D]
__device__ float g_freq[Dc];                 // pos-emb denominators
__device__ float g_w1t[(size_t)NBc*MLPc*Dc]; // W1^T [NB][2048][512]
__device__ float g_w2t[(size_t)NBc*Dc*MLPc]; // W2^T [NB][512][2048]
__device__ float g_wqt[(size_t)NBc*Hc*DHc*DHc]; // Wq^T per head [NB][H][64][64]
__device__ float g_wkt[(size_t)NBc*Hc*DHc*DHc];
__device__ float g_wvt[(size_t)NBc*Hc*DHc*DHc];

// ---------------- mma.sync bf16 helpers (compute_103-safe PTX) -----
__device__ __forceinline__ uint32_t bf16p(float lo, float hi) {
    // pack {lo, hi} -> .b32 with lo in bits[15:0]
    uint32_t u;
    asm("cvt.rn.bf16x2.f32 %0, %1, %2;" : "=r"(u) : "f"(hi), "f"(lo));
    return u;
}
__device__ __forceinline__ void mma_bf16(float* d, const uint32_t* a,
                                         const uint32_t* b) {
    asm volatile("mma.sync.aligned.m16n8k16.row.col.f32.bf16.bf16.f32 "
        "{%0,%1,%2,%3}, {%4,%5,%6,%7}, {%8,%9}, {%0,%1,%2,%3};"
        : "+f"(d[0]), "+f"(d[1]), "+f"(d[2]), "+f"(d[3])
        : "r"(a[0]), "r"(a[1]), "r"(a[2]), "r"(a[3]),
          "r"(b[0]), "r"(b[1]));
}

// ---------------- positional-embedding frequencies (fp64, tiny) ----
__global__ void pe_freq_kernel() {
    int d  = threadIdx.x;
    int je = d & ~1;
    g_freq[d] = (float)pow(10000.0, (double)je / 512.0);
}

// ---------------- embedding: x = src@embW + embb + PE; cls row -----
__global__ __launch_bounds__(128) void embed_kernel(
        const float* __restrict__ src, const float* __restrict__ Wemb,
        const float* __restrict__ bemb, const float* __restrict__ cls) {
    int row = blockIdx.x;               // 0..8191 = b*512 + t
    int b = row >> 9, t = row & 511;
    int tid = threadIdx.x;
    float* xo = g_x + (size_t)row * Dc;
    if (t == 0) {
        #pragma unroll
        for (int kk = 0; kk < 4; kk++) {
            int d = tid + 128*kk;
            xo[d] = cls[d] + ((d & 1) ? 1.0f : 0.0f);  // cos(0)=1, sin(0)=0
        }
        return;
    }
    __shared__ float ss[128];
    ss[tid] = src[((size_t)b*Sc + (t-1))*Fc + tid];
    __syncthreads();
    #pragma unroll
    for (int kk = 0; kk < 4; kk++) {
        int d = tid + 128*kk;
        float acc = bemb[d];
        #pragma unroll 8
        for (int f = 0; f < 128; f++) acc += ss[f] * Wemb[(size_t)f*Dc + d];
        float ang = (float)t / g_freq[d];
        acc += (d & 1) ? cosf(ang) : sinf(ang);
        xo[d] = acc;
    }
}

// ---------------- LayerNorm: g_h = LN(g_x)*g + b -------------------
__global__ __launch_bounds__(128) void ln_kernel(
        const float* __restrict__ gam, const float* __restrict__ bet) {
    int row = blockIdx.x, tid = threadIdx.x;
    const float4* xin = (const float4*)(g_x + (size_t)row*Dc);
    float4 v = xin[tid];
    float s  = v.x+v.y+v.z+v.w;
    float sq = v.x*v.x + v.y*v.y + v.z*v.z + v.w*v.w;
    #pragma unroll
    for (int o = 16; o; o >>= 1) {
        s  += __shfl_xor_sync(0xffffffffu, s,  o);
        sq += __shfl_xor_sync(0xffffffffu, sq, o);
    }
    __shared__ float sm[8];
    if ((tid & 31) == 0) { sm[tid>>5] = s; sm[4 + (tid>>5)] = sq; }
    __syncthreads();
    s  = sm[0]+sm[1]+sm[2]+sm[3];
    sq = sm[4]+sm[5]+sm[6]+sm[7];
    float mean = s * (1.f/512.f);
    float var  = sq * (1.f/512.f) - mean*mean;
    float rstd = rsqrtf(var + 1e-5f);
    float4 g4 = ((const float4*)gam)[tid];
    float4 b4 = ((const float4*)bet)[tid];
    float4 o;
    o.x = (v.x-mean)*rstd*g4.x + b4.x;
    o.y = (v.y-mean)*rstd*g4.y + b4.y;
    o.z = (v.z-mean)*rstd*g4.z + b4.z;
    o.w = (v.w-mean)*rstd*g4.w + b4.w;
    ((float4*)(g_h + (size_t)row*Dc))[tid] = o;
}

// ---------------- weight transpose [K][N] -> [N][K] ----------------
__global__ __launch_bounds__(256) void transpose_kernel(
        const float* __restrict__ W, float* __restrict__ Wt, int K, int N) {
    __shared__ float t[32][33];
    int k0 = blockIdx.y * 32, n0 = blockIdx.x * 32;
    const float* Wb  = W  + (size_t)blockIdx.z * K * N;
    float*       Wtb = Wt + (size_t)blockIdx.z * K * N;
    int x = threadIdx.x, y = threadIdx.y;       // block (32, 8)
    #pragma unroll
    for (int i = 0; i < 32; i += 8)
        t[y+i][x] = Wb[(size_t)(k0+y+i)*N + n0 + x];
    __syncthreads();
    #pragma unroll
    for (int i = 0; i < 32; i += 8)
        Wtb[(size_t)(n0+y+i)*K + k0 + x] = t[x][y+i];
}

// ---------------- bf16 TC QKV projection (64x64, K=64) -------------
// V is written TRANSPOSED: g_v[bh][dh][t]
__global__ __launch_bounds__(128) void qkv_tc_kernel(
        const float* __restrict__ Wqt, const float* __restrict__ bq,
        const float* __restrict__ Wkt, const float* __restrict__ bk,
        const float* __restrict__ Wvt, const float* __restrict__ bv) {
    __shared__ uint32_t Hs[64*36];   // H tile bf16 [t][dh-pair]
    __shared__ uint32_t Ws[64*36];   // W^T tile bf16 [n][k-pair]
    __shared__ float epi[64*65];
    int tid = threadIdx.x, wid = tid >> 5, lane = tid & 31;
    int lr = lane >> 2, lc = lane & 3;
    int bh = blockIdx.y; int b = bh >> 3, h = bh & 7;
    int t0 = blockIdx.x * 64;
    int z  = blockIdx.z;
    const float* Wt   = (z==0 ? Wqt : (z==1 ? Wkt : Wvt)) + (size_t)h*4096;
    const float* bias = (z==0 ? bq  : (z==1 ? bk  : bv )) + h*64;
    float*       out  = (z==0 ? g_q : (z==1 ? g_k : g_v)) + (size_t)bh*Tc*64;

    #pragma unroll
    for (int i = 0; i < 8; i++) {
        int idx = tid + 128*i;                 // 1024 float4
        int row = idx >> 4, c4 = idx & 15;
        float4 hv = *(const float4*)(g_h + ((size_t)(b*Tc) + t0 + row)*Dc
                                     + h*64 + c4*4);
        uint2 hu = { bf16p(hv.x, hv.y), bf16p(hv.z, hv.w) };
        *(uint2*)&Hs[row*36 + c4*2] = hu;
        float4 wv = *(const float4*)(Wt + (size_t)row*64 + c4*4);
        uint2 wu = { bf16p(wv.x, wv.y), bf16p(wv.z, wv.w) };
        *(uint2*)&Ws[row*36 + c4*2] = wu;
    }
    __syncthreads();

    float acc[8][4];
    #pragma unroll
    for (int nf = 0; nf < 8; nf++)
        #pragma unroll
        for (int j = 0; j < 4; j++) acc[nf][j] = 0.f;
    int r0 = wid*16 + lr;
    #pragma unroll
    for (int ks = 0; ks < 4; ks++) {           // K=64 -> 4 k16-steps
        int kb = ks*8 + lc;
        uint32_t af[4];
        af[0] = Hs[r0*36 + kb];
        af[1] = Hs[(r0+8)*36 + kb];
        af[2] = Hs[r0*36 + kb + 4];
        af[3] = Hs[(r0+8)*36 + kb + 4];
        #pragma unroll
        for (int nf = 0; nf < 8; nf++) {
            uint32_t bf[2];
            bf[0] = Ws[(nf*8+lr)*36 + kb];
            bf[1] = Ws[(nf*8+lr)*36 + kb + 4];
            mma_bf16(acc[nf], af, bf);
        }
    }
    #pragma unroll
    for (int nf = 0; nf < 8; nf++) {
        int col = nf*8 + 2*lc;
        float b0v = bias[col], b1v = bias[col+1];
        epi[r0*65 + col]       = acc[nf][0] + b0v;
        epi[r0*65 + col + 1]   = acc[nf][1] + b1v;
        epi[(r0+8)*65 + col]   = acc[nf][2] + b0v;
        epi[(r0+8)*65 + col+1] = acc[nf][3] + b1v;
    }
    __syncthreads();
    if (z == 2) {
        for (int it = 0; it < 32; it++) {      // transposed: out[dh][t]
            int idx = tid + 128*it; int tt = idx & 63, dd = idx >> 6;
            out[(size_t)dd*Tc + t0 + tt] = epi[tt*65 + dd];
        }
    } else {
        for (int it = 0; it < 32; it++) {
            int idx = tid + 128*it; int rr = idx >> 6, cc = idx & 63;
            out[(size_t)(t0+rr)*64 + cc] = epi[rr*65 + cc];
        }
    }
}

// ---------------- bf16 TC flash attention + residual ---------------
// 64 queries/CTA, 4 warps (16 q each), 32-key tiles.
__global__ __launch_bounds__(128) void attn_tc_kernel() {
    __shared__ uint32_t Qs[64*36];      // Q bf16 [q][dh-pair]   9.2KB
    __shared__ uint32_t Ks[32*36];      // K bf16 [key][dh-pair] 4.6KB
    __shared__ uint32_t Vs[64*20];      // V^T bf16 [dh][key-pair] 5.1KB
    __shared__ uint32_t Ps[4][16*20];   // per-warp P bf16       5.1KB
    int tid = threadIdx.x, wid = tid >> 5, lane = tid & 31;
    int lr = lane >> 2, lc = lane & 3;
    int bh = blockIdx.y; int q0 = blockIdx.x * 64;
    const float* qb  = g_q + ((size_t)bh*Tc + q0)*64;
    const float* kbp = g_k + (size_t)bh*Tc*64;
    const float* vtb = g_v + (size_t)bh*64*Tc;   // [dh][t]

    #pragma unroll
    for (int i = 0; i < 8; i++) {
        int idx = tid + 128*i;              // 1024 float4
        int row = idx >> 4, c4 = idx & 15;
        float4 v = *(const float4*)(qb + (size_t)row*64 + c4*4);
        uint2 u = { bf16p(v.x, v.y), bf16p(v.z, v.w) };
        *(uint2*)&Qs[row*36 + c4*2] = u;
    }

    float m0 = -1e30f, m1 = -1e30f, l0 = 0.f, l1 = 0.f;
    float of[8][4];
    #pragma unroll
    for (int nf = 0; nf < 8; nf++)
        #pragma unroll
        for (int j = 0; j < 4; j++) of[nf][j] = 0.f;
    int r0 = wid*16 + lr;

    for (int kt = 0; kt < 16; kt++) {
        int k0 = kt * 32;
        float4 kr[4], vr[4];
        #pragma unroll
        for (int i = 0; i < 4; i++) {
            int idx = tid + 128*i;          // 512 float4 each
            int row = idx >> 4, c4 = idx & 15;
            kr[i] = *(const float4*)(kbp + (size_t)(k0+row)*64 + c4*4);
            int rv = idx >> 3, cv = idx & 7;
            vr[i] = *(const float4*)(vtb + (size_t)rv*Tc + k0 + cv*4);
        }
        __syncthreads();                     // prior tile fully consumed
        #pragma unroll
        for (int i = 0; i < 4; i++) {
            int idx = tid + 128*i;
            int row = idx >> 4, c4 = idx & 15;
            uint2 ku = { bf16p(kr[i].x, kr[i].y), bf16p(kr[i].z, kr[i].w) };
            *(uint2*)&Ks[row*36 + c4*2] = ku;
            int rv = idx >> 3, cv = idx & 7;
            uint2 vu = { bf16p(vr[i].x, vr[i].y), bf16p(vr[i].z, vr[i].w) };
            *(uint2*)&Vs[rv*20 + cv*2] = vu;
        }
        __syncthreads();

        // ---- S = Q K^T (16 q x 32 keys per warp), k=64 ----
        float sf[4][4];
        #pragma unroll
        for (int nf = 0; nf < 4; nf++)
            #pragma unroll
            for (int j = 0; j < 4; j++) sf[nf][j] = 0.f;
        #pragma unroll
        for (int ks = 0; ks < 4; ks++) {
            int kb2 = ks*8 + lc;
            uint32_t qf[4];
            qf[0] = Qs[r0*36 + kb2];
            qf[1] = Qs[(r0+8)*36 + kb2];
            qf[2] = Qs[r0*36 + kb2 + 4];
            qf[3] = Qs[(r0+8)*36 + kb2 + 4];
            #pragma unroll
            for (int nf = 0; nf < 4; nf++) {
                uint32_t bf[2];
                bf[0] = Ks[(nf*8+lr)*36 + kb2];
                bf[1] = Ks[(nf*8+lr)*36 + kb2 + 4];
                mma_bf16(sf[nf], qf, bf);
            }
        }

        // ---- online softmax in fragment layout ----
        float tm0 = -1e30f, tm1 = -1e30f;
        #pragma unroll
        for (int nf = 0; nf < 4; nf++) {
            sf[nf][0] *= 0.125f; sf[nf][1] *= 0.125f;
            sf[nf][2] *= 0.125f; sf[nf][3] *= 0.125f;
            tm0 = fmaxf(tm0, fmaxf(sf[nf][0], sf[nf][1]));
            tm1 = fmaxf(tm1, fmaxf(sf[nf][2], sf[nf][3]));
        }
        tm0 = fmaxf(tm0, __shfl_xor_sync(0xffffffffu, tm0, 1));
        tm0 = fmaxf(tm0, __shfl_xor_sync(0xffffffffu, tm0, 2));
        tm1 = fmaxf(tm1, __shfl_xor_sync(0xffffffffu, tm1, 1));
        tm1 = fmaxf(tm1, __shfl_xor_sync(0xffffffffu, tm1, 2));
        float mn0 = fmaxf(m0, tm0), mn1 = fmaxf(m1, tm1);
        float a0 = __expf(m0 - mn0), a1 = __expf(m1 - mn1);
        float rs0 = 0.f, rs1 = 0.f;
        #pragma unroll
        for (int nf = 0; nf < 4; nf++) {
            float p00 = __expf(sf[nf][0] - mn0), p01 = __expf(sf[nf][1] - mn0);
            float p10 = __expf(sf[nf][2] - mn1), p11 = __expf(sf[nf][3] - mn1);
            rs0 += p00 + p01; rs1 += p10 + p11;
            Ps[wid][lr*20 + nf*4 + lc]     = bf16p(p00, p01);
            Ps[wid][(lr+8)*20 + nf*4 + lc] = bf16p(p10, p11);
        }
        rs0 += __shfl_xor_sync(0xffffffffu, rs0, 1);
        rs0 += __shfl_xor_sync(0xffffffffu, rs0, 2);
        rs1 += __shfl_xor_sync(0xffffffffu, rs1, 1);
        rs1 += __shfl_xor_sync(0xffffffffu, rs1, 2);
        l0 = l0*a0 + rs0; l1 = l1*a1 + rs1;
        m0 = mn0; m1 = mn1;
        #pragma unroll
        for (int nf = 0; nf < 8; nf++) {
            of[nf][0] *= a0; of[nf][1] *= a0;
            of[nf][2] *= a1; of[nf][3] *= a1;
        }
        __syncwarp();                        // P writes -> P reads (same warp)

        // ---- O += P V (16 q x 64 dh per warp), k=32 keys ----
        #pragma unroll
        for (int ks = 0; ks < 2; ks++) {
            int kb2 = ks*8 + lc;
            uint32_t af[4];
            af[0] = Ps[wid][lr*20 + kb2];
            af[1] = Ps[wid][(lr+8)*20 + kb2];
            af[2] = Ps[wid][lr*20 + kb2 + 4];
            af[3] = Ps[wid][(lr+8)*20 + kb2 + 4];
            #pragma unroll
            for (int nf = 0; nf < 8; nf++) {
                uint32_t bf[2];
                bf[0] = Vs[(nf*8+lr)*20 + kb2];
                bf[1] = Vs[(nf*8+lr)*20 + kb2 + 4];
                mma_bf16(of[nf], af, bf);
            }
        }
    }

    // ---- epilogue: normalize + residual add ----
    int b = bh >> 3, h = bh & 7;
    float inv0 = 1.f / l0, inv1 = 1.f / l1;
    int row0 = q0 + r0;
    float* x0 = g_x + ((size_t)(b*Tc) + row0)*Dc + h*64;
    float* x1 = x0 + (size_t)8*Dc;
    #pragma unroll
    for (int nf = 0; nf < 8; nf++) {
        int col = nf*8 + 2*lc;
        float2 o0 = *(float2*)(x0 + col);
        o0.x += of[nf][0]*inv0; o0.y += of[nf][1]*inv0;
        *(float2*)(x0 + col) = o0;
        float2 o1 = *(float2*)(x1 + col);
        o1.x += of[nf][2]*inv1; o1.y += of[nf][3]*inv1;
        *(float2*)(x1 + col) = o1;
    }
}

// ---------------- bf16 TC GEMM, 128x128 tile, double-buffered ------
__device__ __forceinline__ float geluf(float x) {
    return 0.5f * x * (1.0f + erff(x * 0.70710678118654752f));
}

// MODE 0: C = gelu(A@Bt^T + bias)    (FC1)
// MODE 1: C += A@Bt^T + bias         (FC2, residual)
template<int MODE>
__global__ __launch_bounds__(128) void tc_gemm(
        const float* __restrict__ A, const float* __restrict__ Bt,
        const float* __restrict__ bias, float* __restrict__ C,
        int N, int K) {
    __shared__ uint32_t As[2][128*20];   // 10.24KB each, bf16 pairs
    __shared__ uint32_t Bs[2][128*20];
    int tid = threadIdx.x;
    int wid = tid >> 5, lane = tid & 31;
    int wm = wid & 1, wn = wid >> 1;          // 2x2 warps
    int m0 = blockIdx.y * 128, n0 = blockIdx.x * 128;
    int lr = lane >> 2, lc = lane & 3;

    float acc[4][8][4];
    #pragma unroll
    for (int mt = 0; mt < 4; mt++)
        #pragma unroll
        for (int nt = 0; nt < 8; nt++)
            #pragma unroll
            for (int j = 0; j < 4; j++) acc[mt][nt][j] = 0.f;

    const float* Ab = A  + (size_t)m0 * K;
    const float* Bb = Bt + (size_t)n0 * K;
    int nslab = K >> 5;

    float4 ar[8], br[8];
    #pragma unroll
    for (int i = 0; i < 8; i++) {              // prefetch slab 0
        int idx = tid + 128*i;
        int row = idx >> 3, c4 = idx & 7;
        ar[i] = *(const float4*)(Ab + (size_t)row*K + c4*4);
        br[i] = *(const float4*)(Bb + (size_t)row*K + c4*4);
    }

    for (int s = 0; s < nslab; s++) {
        int bsel = s & 1;
        #pragma unroll
        for (int i = 0; i < 8; i++) {          // store slab s
            int idx = tid + 128*i;
            int row = idx >> 3, c4 = idx & 7;
            uint2 au = { bf16p(ar[i].x, ar[i].y), bf16p(ar[i].z, ar[i].w) };
            uint2 bu = { bf16p(br[i].x, br[i].y), bf16p(br[i].z, br[i].w) };
            *(uint2*)&As[bsel][row*20 + c4*2] = au;
            *(uint2*)&Bs[bsel][row*20 + c4*2] = bu;
        }
        if (s + 1 < nslab) {                   // prefetch slab s+1
            #pragma unroll
            for (int i = 0; i < 8; i++) {
                int idx = tid + 128*i;
                int row = idx >> 3, c4 = idx & 7;
                ar[i] = *(const float4*)(Ab + (size_t)row*K + (s+1)*32 + c4*4);
                br[i] = *(const float4*)(Bb + (size_t)row*K + (s+1)*32 + c4*4);
            }
        }
        __syncthreads();
        #pragma unroll
        for (int ks = 0; ks < 2; ks++) {       // 2 x k16 per 32-slab
            int kb = ks*8 + lc;
            uint32_t af[4][4];
            #pragma unroll
            for (int mt = 0; mt < 4; mt++) {
                int r0 = wm*64 + mt*16 + lr;
                af[mt][0] = As[bsel][r0*20 + kb];
                af[mt][1] = As[bsel][(r0+8)*20 + kb];
                af[mt][2] = As[bsel][r0*20 + kb + 4];
                af[mt][3] = As[bsel][(r0+8)*20 + kb + 4];
            }
            #pragma unroll
            for (int nt = 0; nt < 8; nt++) {
                int nr = wn*64 + nt*8 + lr;
                uint32_t bf[2];
                bf[0] = Bs[bsel][nr*20 + kb];
                bf[1] = Bs[bsel][nr*20 + kb + 4];
                #pragma unroll
                for (int mt = 0; mt < 4; mt++)
                    mma_bf16(acc[mt][nt], af[mt], bf);
            }
        }
    }

    #pragma unroll
    for (int mt = 0; mt < 4; mt++) {
        int row = m0 + wm*64 + mt*16 + lr;
        #pragma unroll
        for (int nt = 0; nt < 8; nt++) {
            int col = n0 + wn*64 + nt*8 + lc*2;
            float b0v = bias[col], b1v = bias[col+1];
            float* p0 = C + (size_t)row*N + col;
            float* p1 = C + (size_t)(row+8)*N + col;
            float v0 = acc[mt][nt][0] + b0v, v1 = acc[mt][nt][1] + b1v;
            float v2 = acc[mt][nt][2] + b0v, v3 = acc[mt][nt][3] + b1v;
            if (MODE == 0) {
                v0 = geluf(v0); v1 = geluf(v1); v2 = geluf(v2); v3 = geluf(v3);
            } else {
                float2 o0 = *(const float2*)p0;
                float2 o1 = *(const float2*)p1;
                v0 += o0.x; v1 += o0.y; v2 += o1.x; v3 += o1.y;
            }
            float2 r0 = {v0, v1}, r1 = {v2, v3};
            *(float2*)p0 = r0;
            *(float2*)p1 = r1;
        }
    }
}

// ---------------- classifier head ---------------------------------
__global__ __launch_bounds__(512) void head_kernel(
        const float* __restrict__ hW, const float* __restrict__ hb,
        float* __restrict__ out) {
    int w = threadIdx.x >> 5, lane = threadIdx.x & 31;
    const float* xr = g_x + (size_t)w * Tc * Dc;
    float s = 0.f;
    for (int d = lane; d < Dc; d += 32) s += xr[d] * hW[d];
    #pragma unroll
    for (int o = 16; o; o >>= 1) s += __shfl_xor_sync(0xffffffffu, s, o);
    if (lane == 0) out[w] = 1.f / (1.f + expf(-(s + hb[0])));
}

// ---------------- launcher -----------------------------------------
extern "C" void kernel_launch(void* const* d_in, const int* in_sizes, int n_in,
                              void* d_out, int out_size) {
    const float* src  = (const float*)d_in[0];
    const float* embW = (const float*)d_in[1];
    const float* embb = (const float*)d_in[2];
    const float* cls  = (const float*)d_in[3];
    const float* ln1g = (const float*)d_in[4];
    const float* ln1b = (const float*)d_in[5];
    const float* Wq   = (const float*)d_in[6];
    const float* bq   = (const float*)d_in[7];
    const float* Wk   = (const float*)d_in[8];
    const float* bk   = (const float*)d_in[9];
    const float* Wv   = (const float*)d_in[10];
    const float* bv   = (const float*)d_in[11];
    const float* ln2g = (const float*)d_in[12];
    const float* ln2b = (const float*)d_in[13];
    const float* W1   = (const float*)d_in[14];
    const float* b1   = (const float*)d_in[15];
    const float* W2   = (const float*)d_in[16];
    const float* b2   = (const float*)d_in[17];
    const float* hW   = (const float*)d_in[18];
    const float* hb   = (const float*)d_in[19];
    float* out = (float*)d_out;

    float *ph, *pm1, *px, *pw1t, *pw2t, *pwqt, *pwkt, *pwvt;
    cudaGetSymbolAddress((void**)&ph,   g_h);
    cudaGetSymbolAddress((void**)&pm1,  g_m1);
    cudaGetSymbolAddress((void**)&px,   g_x);
    cudaGetSymbolAddress((void**)&pw1t, g_w1t);
    cudaGetSymbolAddress((void**)&pw2t, g_w2t);
    cudaGetSymbolAddress((void**)&pwqt, g_wqt);
    cudaGetSymbolAddress((void**)&pwkt, g_wkt);
    cudaGetSymbolAddress((void**)&pwvt, g_wvt);

    pe_freq_kernel<<<1, 512>>>();
    transpose_kernel<<<dim3(MLPc/32, Dc/32, NBc), dim3(32,8)>>>(W1, pw1t, Dc, MLPc);
    transpose_kernel<<<dim3(Dc/32, MLPc/32, NBc), dim3(32,8)>>>(W2, pw2t, MLPc, Dc);
    transpose_kernel<<<dim3(2, 2, NBc*Hc), dim3(32,8)>>>(Wq, pwqt, DHc, DHc);
    transpose_kernel<<<dim3(2, 2, NBc*Hc), dim3(32,8)>>>(Wk, pwkt, DHc, DHc);
    transpose_kernel<<<dim3(2, 2, NBc*Hc), dim3(32,8)>>>(Wv, pwvt, DHc, DHc);
    embed_kernel<<<BTc, 128>>>(src, embW, embb, cls);
    for (int i = 0; i < NBc; i++) {
        size_t wo = (size_t)i*Hc*DHc*DHc, bo = (size_t)i*Hc*DHc;
        ln_kernel<<<BTc, 128>>>(ln1g + i*Dc, ln1b + i*Dc);
        qkv_tc_kernel<<<dim3(Tc/64, Bc*Hc, 3), 128>>>(
            pwqt + wo, bq + bo, pwkt + wo, bk + bo, pwvt + wo, bv + bo);
        attn_tc_kernel<<<dim3(Tc/64, Bc*Hc), 128>>>();
        ln_kernel<<<BTc, 128>>>(ln2g + i*Dc, ln2b + i*Dc);
        tc_gemm<0><<<dim3(MLPc/128, BTc/128), 128>>>(
            ph, pw1t + (size_t)i*MLPc*Dc, b1 + (size_t)i*MLPc, pm1, MLPc, Dc);
        tc_gemm<1><<<dim3(Dc/128, BTc/128), 128>>>(
            pm1, pw2t + (size_t)i*Dc*MLPc, b2 + (size_t)i*Dc, px, Dc, MLPc);
    }
    head_kernel<<<1, 512>>>(hW, hb, out);
}

// round 17
// speedup vs baseline: 4.0976x; 1.0151x over previous
#include <cuda_runtime.h>
#include <math.h>
#include <stdint.h>

// Problem dims
#define Bc   16
#define Sc   511
#define Fc   128
#define Dc   512
#define Hc   8
#define DHc  64
#define NBc  6
#define MLPc 2048
#define Tc   512
#define BTc  (Bc*Tc)   // 8192

// ---------------- scratch (no allocations allowed) ----------------
__device__ float g_x[(size_t)BTc*Dc];        // residual stream  [B*T, D]
__device__ float g_h[(size_t)BTc*Dc];        // LN output        [B*T, D]
__device__ float g_q[(size_t)Bc*Hc*Tc*DHc];  // [B*H, T, DH]
__device__ float g_k[(size_t)Bc*Hc*Tc*DHc];  // [B*H, T, DH]
__device__ float g_v[(size_t)Bc*Hc*Tc*DHc];  // [B*H, DH, T]  (TRANSPOSED)
__device__ float g_m1[(size_t)BTc*MLPc];     // MLP hidden [B*T, 4D]
__device__ float g_freq[Dc];                 // pos-emb denominators
__device__ float g_w1t[(size_t)NBc*MLPc*Dc]; // W1^T [NB][2048][512]
__device__ float g_w2t[(size_t)NBc*Dc*MLPc]; // W2^T [NB][512][2048]
__device__ float g_wqt[(size_t)NBc*Hc*DHc*DHc]; // Wq^T per head
__device__ float g_wkt[(size_t)NBc*Hc*DHc*DHc];
__device__ float g_wvt[(size_t)NBc*Hc*DHc*DHc];
__device__ float g_wet[(size_t)Dc*Fc];       // embW^T [D][F]

// ---------------- mma.sync helpers (compute_103-safe PTX) ----------
__device__ __forceinline__ uint32_t bf16p(float lo, float hi) {
    uint32_t u;
    asm("cvt.rn.bf16x2.f32 %0, %1, %2;" : "=r"(u) : "f"(hi), "f"(lo));
    return u;
}
__device__ __forceinline__ void mma_bf16(float* d, const uint32_t* a,
                                         const uint32_t* b) {
    asm volatile("mma.sync.aligned.m16n8k16.row.col.f32.bf16.bf16.f32 "
        "{%0,%1,%2,%3}, {%4,%5,%6,%7}, {%8,%9}, {%0,%1,%2,%3};"
        : "+f"(d[0]), "+f"(d[1]), "+f"(d[2]), "+f"(d[3])
        : "r"(a[0]), "r"(a[1]), "r"(a[2]), "r"(a[3]),
          "r"(b[0]), "r"(b[1]));
}
__device__ __forceinline__ uint32_t tf32u(float x) {
    uint32_t u; asm("cvt.rna.tf32.f32 %0, %1;" : "=r"(u) : "f"(x));
    return u;
}
__device__ __forceinline__ void mma_tf32(float* d, const uint32_t* a,
                                         const uint32_t* b) {
    asm volatile("mma.sync.aligned.m16n8k8.row.col.f32.tf32.tf32.f32 "
        "{%0,%1,%2,%3}, {%4,%5,%6,%7}, {%8,%9}, {%0,%1,%2,%3};"
        : "+f"(d[0]), "+f"(d[1]), "+f"(d[2]), "+f"(d[3])
        : "r"(a[0]), "r"(a[1]), "r"(a[2]), "r"(a[3]),
          "r"(b[0]), "r"(b[1]));
}

// ---------------- positional-embedding frequencies (fp64, tiny) ----
__global__ void pe_freq_kernel() {
    int d  = threadIdx.x;
    int je = d & ~1;
    g_freq[d] = (float)pow(10000.0, (double)je / 512.0);
}

// ---------------- cls rows: x[b,0,:] = cls + PE(0) -----------------
__global__ __launch_bounds__(128) void embed_cls_kernel(
        const float* __restrict__ cls) {
    int b = blockIdx.x, tid = threadIdx.x;
    float* xo = g_x + (size_t)(b*Tc) * Dc;
    #pragma unroll
    for (int kk = 0; kk < 4; kk++) {
        int d = tid + 128*kk;
        xo[d] = cls[d] + ((d & 1) ? 1.0f : 0.0f);   // cos(0)=1, sin(0)=0
    }
}

// ---------------- TC tf32 embedding GEMM + PE + bias ---------------
// x[b*512+t, :] = src[b*511+t-1, :] @ embW + bemb + PE(t)   (t >= 1)
// A: virtual [BT,128] (row-remapped src); B: g_wet [D][F] K-major.
__global__ __launch_bounds__(128) void embed_tc_kernel(
        const float* __restrict__ src, const float* __restrict__ Wet,
        const float* __restrict__ bemb) {
    __shared__ uint32_t As[128*36];   // tf32, stride-36 conflict-free
    __shared__ uint32_t Bs[128*36];
    int tid = threadIdx.x;
    int wid = tid >> 5, lane = tid & 31;
    int wm = wid & 1, wn = wid >> 1;
    int m0 = blockIdx.y * 128, n0 = blockIdx.x * 128;
    int lr = lane >> 2, lc = lane & 3;
    int b = m0 >> 9, t0 = m0 & 511;          // tile within one batch
    const float* srcb = src + (size_t)b*Sc*Fc;

    float acc[4][8][4];
    #pragma unroll
    for (int mt = 0; mt < 4; mt++)
        #pragma unroll
        for (int nt = 0; nt < 8; nt++)
            #pragma unroll
            for (int j = 0; j < 4; j++) acc[mt][nt][j] = 0.f;

    for (int s = 0; s < 4; s++) {            // K=128, 32-slabs
        float4 ar[8], br[8];
        #pragma unroll
        for (int i = 0; i < 8; i++) {
            int idx = tid + 128*i;
            int row = idx >> 3, c4 = idx & 7;
            int t = t0 + row;
            if (t >= 1) {
                ar[i] = *(const float4*)(srcb + (size_t)(t-1)*Fc + s*32 + c4*4);
            } else {
                ar[i] = make_float4(0.f, 0.f, 0.f, 0.f);
            }
            br[i] = *(const float4*)(Wet + (size_t)(n0+row)*Fc + s*32 + c4*4);
        }
        __syncthreads();
        #pragma unroll
        for (int i = 0; i < 8; i++) {
            int idx = tid + 128*i;
            int row = idx >> 3, c4 = idx & 7;
            uint4 av = { tf32u(ar[i].x), tf32u(ar[i].y),
                         tf32u(ar[i].z), tf32u(ar[i].w) };
            uint4 bv = { tf32u(br[i].x), tf32u(br[i].y),
                         tf32u(br[i].z), tf32u(br[i].w) };
            *(uint4*)&As[row*36 + c4*4] = av;
            *(uint4*)&Bs[row*36 + c4*4] = bv;
        }
        __syncthreads();
        #pragma unroll
        for (int ks = 0; ks < 4; ks++) {
            int kb = ks*8 + lc;
            uint32_t af[4][4];
            #pragma unroll
            for (int mt = 0; mt < 4; mt++) {
                int r0 = wm*64 + mt*16 + lr;
                af[mt][0] = As[r0*36 + kb];
                af[mt][1] = As[(r0+8)*36 + kb];
                af[mt][2] = As[r0*36 + kb + 4];
                af[mt][3] = As[(r0+8)*36 + kb + 4];
            }
            #pragma unroll
            for (int nt = 0; nt < 8; nt++) {
                int nr = wn*64 + nt*8 + lr;
                uint32_t bf[2];
                bf[0] = Bs[nr*36 + kb];
                bf[1] = Bs[nr*36 + kb + 4];
                #pragma unroll
                for (int mt = 0; mt < 4; mt++)
                    mma_tf32(acc[mt][nt], af[mt], bf);
            }
        }
        __syncthreads();
    }

    // epilogue: + bemb + PE(t); skip t==0 rows (cls kernel owns them)
    #pragma unroll
    for (int mt = 0; mt < 4; mt++) {
        int lrow = wm*64 + mt*16 + lr;
        #pragma unroll
        for (int half = 0; half < 2; half++) {
            int t = t0 + lrow + half*8;
            if (t < 1) continue;
            float* xrow = g_x + (size_t)(m0 + lrow + half*8)*Dc;
            float ft = (float)t;
            #pragma unroll
            for (int nt = 0; nt < 8; nt++) {
                int col = n0 + wn*64 + nt*8 + lc*2;   // even col
                float ang0 = ft / g_freq[col];
                float ang1 = ft / g_freq[col+1];
                float2 rv;
                rv.x = acc[mt][nt][half*2+0] + bemb[col]   + sinf(ang0);
                rv.y = acc[mt][nt][half*2+1] + bemb[col+1] + cosf(ang1);
                *(float2*)(xrow + col) = rv;
            }
        }
    }
}

// ---------------- LayerNorm: warp-per-row, 4 rows/CTA --------------
__global__ __launch_bounds__(128) void ln_kernel(
        const float* __restrict__ gam, const float* __restrict__ bet) {
    int w = threadIdx.x >> 5, lane = threadIdx.x & 31;
    int row = blockIdx.x*4 + w;
    const float4* xin = (const float4*)(g_x + (size_t)row*Dc);
    float4 v[4];
    float s = 0.f, sq = 0.f;
    #pragma unroll
    for (int j = 0; j < 4; j++) {
        v[j] = xin[lane + 32*j];
        s  += v[j].x + v[j].y + v[j].z + v[j].w;
        sq += v[j].x*v[j].x + v[j].y*v[j].y + v[j].z*v[j].z + v[j].w*v[j].w;
    }
    #pragma unroll
    for (int o = 16; o; o >>= 1) {
        s  += __shfl_xor_sync(0xffffffffu, s,  o);
        sq += __shfl_xor_sync(0xffffffffu, sq, o);
    }
    float mean = s * (1.f/512.f);
    float var  = sq * (1.f/512.f) - mean*mean;
    float rstd = rsqrtf(var + 1e-5f);
    float4* hout = (float4*)(g_h + (size_t)row*Dc);
    const float4* g4p = (const float4*)gam;
    const float4* b4p = (const float4*)bet;
    #pragma unroll
    for (int j = 0; j < 4; j++) {
        float4 g4 = g4p[lane + 32*j];
        float4 b4 = b4p[lane + 32*j];
        float4 o;
        o.x = (v[j].x-mean)*rstd*g4.x + b4.x;
        o.y = (v[j].y-mean)*rstd*g4.y + b4.y;
        o.z = (v[j].z-mean)*rstd*g4.z + b4.z;
        o.w = (v[j].w-mean)*rstd*g4.w + b4.w;
        hout[lane + 32*j] = o;
    }
}

// ---------------- weight transpose [K][N] -> [N][K] ----------------
__global__ __launch_bounds__(256) void transpose_kernel(
        const float* __restrict__ W, float* __restrict__ Wt, int K, int N) {
    __shared__ float t[32][33];
    int k0 = blockIdx.y * 32, n0 = blockIdx.x * 32;
    const float* Wb  = W  + (size_t)blockIdx.z * K * N;
    float*       Wtb = Wt + (size_t)blockIdx.z * K * N;
    int x = threadIdx.x, y = threadIdx.y;       // block (32, 8)
    #pragma unroll
    for (int i = 0; i < 32; i += 8)
        t[y+i][x] = Wb[(size_t)(k0+y+i)*N + n0 + x];
    __syncthreads();
    #pragma unroll
    for (int i = 0; i < 32; i += 8)
        Wtb[(size_t)(n0+y+i)*K + k0 + x] = t[x][y+i];
}

// ---------------- bf16 TC QKV projection (64x64, K=64) -------------
// V is written TRANSPOSED: g_v[bh][dh][t]
__global__ __launch_bounds__(128) void qkv_tc_kernel(
        const float* __restrict__ Wqt, const float* __restrict__ bq,
        const float* __restrict__ Wkt, const float* __restrict__ bk,
        const float* __restrict__ Wvt, const float* __restrict__ bv) {
    __shared__ uint32_t Hs[64*36];   // H tile bf16 [t][dh-pair]
    __shared__ uint32_t Ws[64*36];   // W^T tile bf16 [n][k-pair]
    __shared__ float epi[64*65];
    int tid = threadIdx.x, wid = tid >> 5, lane = tid & 31;
    int lr = lane >> 2, lc = lane & 3;
    int bh = blockIdx.y; int b = bh >> 3, h = bh & 7;
    int t0 = blockIdx.x * 64;
    int z  = blockIdx.z;
    const float* Wt   = (z==0 ? Wqt : (z==1 ? Wkt : Wvt)) + (size_t)h*4096;
    const float* bias = (z==0 ? bq  : (z==1 ? bk  : bv )) + h*64;
    float*       out  = (z==0 ? g_q : (z==1 ? g_k : g_v)) + (size_t)bh*Tc*64;

    #pragma unroll
    for (int i = 0; i < 8; i++) {
        int idx = tid + 128*i;                 // 1024 float4
        int row = idx >> 4, c4 = idx & 15;
        float4 hv = *(const float4*)(g_h + ((size_t)(b*Tc) + t0 + row)*Dc
                                     + h*64 + c4*4);
        uint2 hu = { bf16p(hv.x, hv.y), bf16p(hv.z, hv.w) };
        *(uint2*)&Hs[row*36 + c4*2] = hu;
        float4 wv = *(const float4*)(Wt + (size_t)row*64 + c4*4);
        uint2 wu = { bf16p(wv.x, wv.y), bf16p(wv.z, wv.w) };
        *(uint2*)&Ws[row*36 + c4*2] = wu;
    }
    __syncthreads();

    float acc[8][4];
    #pragma unroll
    for (int nf = 0; nf < 8; nf++)
        #pragma unroll
        for (int j = 0; j < 4; j++) acc[nf][j] = 0.f;
    int r0 = wid*16 + lr;
    #pragma unroll
    for (int ks = 0; ks < 4; ks++) {           // K=64 -> 4 k16-steps
        int kb = ks*8 + lc;
        uint32_t af[4];
        af[0] = Hs[r0*36 + kb];
        af[1] = Hs[(r0+8)*36 + kb];
        af[2] = Hs[r0*36 + kb + 4];
        af[3] = Hs[(r0+8)*36 + kb + 4];
        #pragma unroll
        for (int nf = 0; nf < 8; nf++) {
            uint32_t bf[2];
            bf[0] = Ws[(nf*8+lr)*36 + kb];
            bf[1] = Ws[(nf*8+lr)*36 + kb + 4];
            mma_bf16(acc[nf], af, bf);
        }
    }
    #pragma unroll
    for (int nf = 0; nf < 8; nf++) {
        int col = nf*8 + 2*lc;
        float b0v = bias[col], b1v = bias[col+1];
        epi[r0*65 + col]       = acc[nf][0] + b0v;
        epi[r0*65 + col + 1]   = acc[nf][1] + b1v;
        epi[(r0+8)*65 + col]   = acc[nf][2] + b0v;
        epi[(r0+8)*65 + col+1] = acc[nf][3] + b1v;
    }
    __syncthreads();
    if (z == 2) {
        for (int it = 0; it < 32; it++) {      // transposed: out[dh][t]
            int idx = tid + 128*it; int tt = idx & 63, dd = idx >> 6;
            out[(size_t)dd*Tc + t0 + tt] = epi[tt*65 + dd];
        }
    } else {
        for (int it = 0; it < 32; it++) {
            int idx = tid + 128*it; int rr = idx >> 6, cc = idx & 63;
            out[(size_t)(t0+rr)*64 + cc] = epi[rr*65 + cc];
        }
    }
}

// ---------------- bf16 TC flash attention + residual ---------------
// 64 queries/CTA, 4 warps (16 q each), 32-key tiles.
__global__ __launch_bounds__(128) void attn_tc_kernel() {
    __shared__ uint32_t Qs[64*36];      // Q bf16 [q][dh-pair]
    __shared__ uint32_t Ks[32*36];      // K bf16 [key][dh-pair]
    __shared__ uint32_t Vs[64*20];      // V^T bf16 [dh][key-pair]
    __shared__ uint32_t Ps[4][16*20];   // per-warp P bf16
    int tid = threadIdx.x, wid = tid >> 5, lane = tid & 31;
    int lr = lane >> 2, lc = lane & 3;
    int bh = blockIdx.y; int q0 = blockIdx.x * 64;
    const float* qb  = g_q + ((size_t)bh*Tc + q0)*64;
    const float* kbp = g_k + (size_t)bh*Tc*64;
    const float* vtb = g_v + (size_t)bh*64*Tc;   // [dh][t]

    #pragma unroll
    for (int i = 0; i < 8; i++) {
        int idx = tid + 128*i;              // 1024 float4
        int row = idx >> 4, c4 = idx & 15;
        float4 v = *(const float4*)(qb + (size_t)row*64 + c4*4);
        uint2 u = { bf16p(v.x, v.y), bf16p(v.z, v.w) };
        *(uint2*)&Qs[row*36 + c4*2] = u;
    }

    float m0 = -1e30f, m1 = -1e30f, l0 = 0.f, l1 = 0.f;
    float of[8][4];
    #pragma unroll
    for (int nf = 0; nf < 8; nf++)
        #pragma unroll
        for (int j = 0; j < 4; j++) of[nf][j] = 0.f;
    int r0 = wid*16 + lr;

    for (int kt = 0; kt < 16; kt++) {
        int k0 = kt * 32;
        float4 kr[4], vr[4];
        #pragma unroll
        for (int i = 0; i < 4; i++) {
            int idx = tid + 128*i;          // 512 float4 each
            int row = idx >> 4, c4 = idx & 15;
            kr[i] = *(const float4*)(kbp + (size_t)(k0+row)*64 + c4*4);
            int rv = idx >> 3, cv = idx & 7;
            vr[i] = *(const float4*)(vtb + (size_t)rv*Tc + k0 + cv*4);
        }
        __syncthreads();                     // prior tile fully consumed
        #pragma unroll
        for (int i = 0; i < 4; i++) {
            int idx = tid + 128*i;
            int row = idx >> 4, c4 = idx & 15;
            uint2 ku = { bf16p(kr[i].x, kr[i].y), bf16p(kr[i].z, kr[i].w) };
            *(uint2*)&Ks[row*36 + c4*2] = ku;
            int rv = idx >> 3, cv = idx & 7;
            uint2 vu = { bf16p(vr[i].x, vr[i].y), bf16p(vr[i].z, vr[i].w) };
            *(uint2*)&Vs[rv*20 + cv*2] = vu;
        }
        __syncthreads();

        // ---- S = Q K^T (16 q x 32 keys per warp), k=64 ----
        float sf[4][4];
        #pragma unroll
        for (int nf = 0; nf < 4; nf++)
            #pragma unroll
            for (int j = 0; j < 4; j++) sf[nf][j] = 0.f;
        #pragma unroll
        for (int ks = 0; ks < 4; ks++) {
            int kb2 = ks*8 + lc;
            uint32_t qf[4];
            qf[0] = Qs[r0*36 + kb2];
            qf[1] = Qs[(r0+8)*36 + kb2];
            qf[2] = Qs[r0*36 + kb2 + 4];
            qf[3] = Qs[(r0+8)*36 + kb2 + 4];
            #pragma unroll
            for (int nf = 0; nf < 4; nf++) {
                uint32_t bf[2];
                bf[0] = Ks[(nf*8+lr)*36 + kb2];
                bf[1] = Ks[(nf*8+lr)*36 + kb2 + 4];
                mma_bf16(sf[nf], qf, bf);
            }
        }

        // ---- online softmax in fragment layout ----
        float tm0 = -1e30f, tm1 = -1e30f;
        #pragma unroll
        for (int nf = 0; nf < 4; nf++) {
            sf[nf][0] *= 0.125f; sf[nf][1] *= 0.125f;
            sf[nf][2] *= 0.125f; sf[nf][3] *= 0.125f;
            tm0 = fmaxf(tm0, fmaxf(sf[nf][0], sf[nf][1]));
            tm1 = fmaxf(tm1, fmaxf(sf[nf][2], sf[nf][3]));
        }
        tm0 = fmaxf(tm0, __shfl_xor_sync(0xffffffffu, tm0, 1));
        tm0 = fmaxf(tm0, __shfl_xor_sync(0xffffffffu, tm0, 2));
        tm1 = fmaxf(tm1, __shfl_xor_sync(0xffffffffu, tm1, 1));
        tm1 = fmaxf(tm1, __shfl_xor_sync(0xffffffffu, tm1, 2));
        float mn0 = fmaxf(m0, tm0), mn1 = fmaxf(m1, tm1);
        float a0 = __expf(m0 - mn0), a1 = __expf(m1 - mn1);
        float rs0 = 0.f, rs1 = 0.f;
        #pragma unroll
        for (int nf = 0; nf < 4; nf++) {
            float p00 = __expf(sf[nf][0] - mn0), p01 = __expf(sf[nf][1] - mn0);
            float p10 = __expf(sf[nf][2] - mn1), p11 = __expf(sf[nf][3] - mn1);
            rs0 += p00 + p01; rs1 += p10 + p11;
            Ps[wid][lr*20 + nf*4 + lc]     = bf16p(p00, p01);
            Ps[wid][(lr+8)*20 + nf*4 + lc] = bf16p(p10, p11);
        }
        rs0 += __shfl_xor_sync(0xffffffffu, rs0, 1);
        rs0 += __shfl_xor_sync(0xffffffffu, rs0, 2);
        rs1 += __shfl_xor_sync(0xffffffffu, rs1, 1);
        rs1 += __shfl_xor_sync(0xffffffffu, rs1, 2);
        l0 = l0*a0 + rs0; l1 = l1*a1 + rs1;
        m0 = mn0; m1 = mn1;
        #pragma unroll
        for (int nf = 0; nf < 8; nf++) {
            of[nf][0] *= a0; of[nf][1] *= a0;
            of[nf][2] *= a1; of[nf][3] *= a1;
        }
        __syncwarp();                        // P writes -> P reads (same warp)

        // ---- O += P V (16 q x 64 dh per warp), k=32 keys ----
        #pragma unroll
        for (int ks = 0; ks < 2; ks++) {
            int kb2 = ks*8 + lc;
            uint32_t af[4];
            af[0] = Ps[wid][lr*20 + kb2];
            af[1] = Ps[wid][(lr+8)*20 + kb2];
            af[2] = Ps[wid][lr*20 + kb2 + 4];
            af[3] = Ps[wid][(lr+8)*20 + kb2 + 4];
            #pragma unroll
            for (int nf = 0; nf < 8; nf++) {
                uint32_t bf[2];
                bf[0] = Vs[(nf*8+lr)*20 + kb2];
                bf[1] = Vs[(nf*8+lr)*20 + kb2 + 4];
                mma_bf16(of[nf], af, bf);
            }
        }
    }

    // ---- epilogue: normalize + residual add ----
    int b = bh >> 3, h = bh & 7;
    float inv0 = 1.f / l0, inv1 = 1.f / l1;
    int row0 = q0 + r0;
    float* x0 = g_x + ((size_t)(b*Tc) + row0)*Dc + h*64;
    float* x1 = x0 + (size_t)8*Dc;
    #pragma unroll
    for (int nf = 0; nf < 8; nf++) {
        int col = nf*8 + 2*lc;
        float2 o0 = *(float2*)(x0 + col);
        o0.x += of[nf][0]*inv0; o0.y += of[nf][1]*inv0;
        *(float2*)(x0 + col) = o0;
        float2 o1 = *(float2*)(x1 + col);
        o1.x += of[nf][2]*inv1; o1.y += of[nf][3]*inv1;
        *(float2*)(x1 + col) = o1;
    }
}

// ---------------- bf16 TC GEMM, 128x128 tile, double-buffered ------
__device__ __forceinline__ float geluf(float x) {
    return 0.5f * x * (1.0f + erff(x * 0.70710678118654752f));
}

// MODE 0: C = gelu(A@Bt^T + bias)    (FC1)
// MODE 1: C += A@Bt^T + bias         (FC2, residual)
template<int MODE>
__global__ __launch_bounds__(128) void tc_gemm(
        const float* __restrict__ A, const float* __restrict__ Bt,
        const float* __restrict__ bias, float* __restrict__ C,
        int N, int K) {
    __shared__ uint32_t As[2][128*20];   // bf16 pairs
    __shared__ uint32_t Bs[2][128*20];
    int tid = threadIdx.x;
    int wid = tid >> 5, lane = tid & 31;
    int wm = wid & 1, wn = wid >> 1;          // 2x2 warps
    int m0 = blockIdx.y * 128, n0 = blockIdx.x * 128;
    int lr = lane >> 2, lc = lane & 3;

    float acc[4][8][4];
    #pragma unroll
    for (int mt = 0; mt < 4; mt++)
        #pragma unroll
        for (int nt = 0; nt < 8; nt++)
            #pragma unroll
            for (int j = 0; j < 4; j++) acc[mt][nt][j] = 0.f;

    const float* Ab = A  + (size_t)m0 * K;
    const float* Bb = Bt + (size_t)n0 * K;
    int nslab = K >> 5;

    float4 ar[8], br[8];
    #pragma unroll
    for (int i = 0; i < 8; i++) {              // prefetch slab 0
        int idx = tid + 128*i;
        int row = idx >> 3, c4 = idx & 7;
        ar[i] = *(const float4*)(Ab + (size_t)row*K + c4*4);
        br[i] = *(const float4*)(Bb + (size_t)row*K + c4*4);
    }

    for (int s = 0; s < nslab; s++) {
        int bsel = s & 1;
        #pragma unroll
        for (int i = 0; i < 8; i++) {          // store slab s
            int idx = tid + 128*i;
            int row = idx >> 3, c4 = idx & 7;
            uint2 au = { bf16p(ar[i].x, ar[i].y), bf16p(ar[i].z, ar[i].w) };
            uint2 bu = { bf16p(br[i].x, br[i].y), bf16p(br[i].z, br[i].w) };
            *(uint2*)&As[bsel][row*20 + c4*2] = au;
            *(uint2*)&Bs[bsel][row*20 + c4*2] = bu;
        }
        if (s + 1 < nslab) {                   // prefetch slab s+1
            #pragma unroll
            for (int i = 0; i < 8; i++) {
                int idx = tid + 128*i;
                int row = idx >> 3, c4 = idx & 7;
                ar[i] = *(const float4*)(Ab + (size_t)row*K + (s+1)*32 + c4*4);
                br[i] = *(const float4*)(Bb + (size_t)row*K + (s+1)*32 + c4*4);
            }
        }
        __syncthreads();
        #pragma unroll
        for (int ks = 0; ks < 2; ks++) {       // 2 x k16 per 32-slab
            int kb = ks*8 + lc;
            uint32_t af[4][4];
            #pragma unroll
            for (int mt = 0; mt < 4; mt++) {
                int r0 = wm*64 + mt*16 + lr;
                af[mt][0] = As[bsel][r0*20 + kb];
                af[mt][1] = As[bsel][(r0+8)*20 + kb];
                af[mt][2] = As[bsel][r0*20 + kb + 4];
                af[mt][3] = As[bsel][(r0+8)*20 + kb + 4];
            }
            #pragma unroll
            for (int nt = 0; nt < 8; nt++) {
                int nr = wn*64 + nt*8 + lr;
                uint32_t bf[2];
                bf[0] = Bs[bsel][nr*20 + kb];
                bf[1] = Bs[bsel][nr*20 + kb + 4];
                #pragma unroll
                for (int mt = 0; mt < 4; mt++)
                    mma_bf16(acc[mt][nt], af[mt], bf);
            }
        }
    }

    #pragma unroll
    for (int mt = 0; mt < 4; mt++) {
        int row = m0 + wm*64 + mt*16 + lr;
        #pragma unroll
        for (int nt = 0; nt < 8; nt++) {
            int col = n0 + wn*64 + nt*8 + lc*2;
            float b0v = bias[col], b1v = bias[col+1];
            float* p0 = C + (size_t)row*N + col;
            float* p1 = C + (size_t)(row+8)*N + col;
            float v0 = acc[mt][nt][0] + b0v, v1 = acc[mt][nt][1] + b1v;
            float v2 = acc[mt][nt][2] + b0v, v3 = acc[mt][nt][3] + b1v;
            if (MODE == 0) {
                v0 = geluf(v0); v1 = geluf(v1); v2 = geluf(v2); v3 = geluf(v3);
            } else {
                float2 o0 = *(const float2*)p0;
                float2 o1 = *(const float2*)p1;
                v0 += o0.x; v1 += o0.y; v2 += o1.x; v3 += o1.y;
            }
            float2 r0 = {v0, v1}, r1 = {v2, v3};
            *(float2*)p0 = r0;
            *(float2*)p1 = r1;
        }
    }
}

// ---------------- classifier head ---------------------------------
__global__ __launch_bounds__(512) void head_kernel(
        const float* __restrict__ hW, const float* __restrict__ hb,
        float* __restrict__ out) {
    int w = threadIdx.x >> 5, lane = threadIdx.x & 31;
    const float* xr = g_x + (size_t)w * Tc * Dc;
    float s = 0.f;
    for (int d = lane; d < Dc; d += 32) s += xr[d] * hW[d];
    #pragma unroll
    for (int o = 16; o; o >>= 1) s += __shfl_xor_sync(0xffffffffu, s, o);
    if (lane == 0) out[w] = 1.f / (1.f + expf(-(s + hb[0])));
}

// ---------------- launcher -----------------------------------------
extern "C" void kernel_launch(void* const* d_in, const int* in_sizes, int n_in,
                              void* d_out, int out_size) {
    const float* src  = (const float*)d_in[0];
    const float* embW = (const float*)d_in[1];
    const float* embb = (const float*)d_in[2];
    const float* cls  = (const float*)d_in[3];
    const float* ln1g = (const float*)d_in[4];
    const float* ln1b = (const float*)d_in[5];
    const float* Wq   = (const float*)d_in[6];
    const float* bq   = (const float*)d_in[7];
    const float* Wk   = (const float*)d_in[8];
    const float* bk   = (const float*)d_in[9];
    const float* Wv   = (const float*)d_in[10];
    const float* bv   = (const float*)d_in[11];
    const float* ln2g = (const float*)d_in[12];
    const float* ln2b = (const float*)d_in[13];
    const float* W1   = (const float*)d_in[14];
    const float* b1   = (const float*)d_in[15];
    const float* W2   = (const float*)d_in[16];
    const float* b2   = (const float*)d_in[17];
    const float* hW   = (const float*)d_in[18];
    const float* hb   = (const float*)d_in[19];
    float* out = (float*)d_out;

    float *ph, *pm1, *px, *pw1t, *pw2t, *pwqt, *pwkt, *pwvt, *pwet;
    cudaGetSymbolAddress((void**)&ph,   g_h);
    cudaGetSymbolAddress((void**)&pm1,  g_m1);
    cudaGetSymbolAddress((void**)&px,   g_x);
    cudaGetSymbolAddress((void**)&pw1t, g_w1t);
    cudaGetSymbolAddress((void**)&pw2t, g_w2t);
    cudaGetSymbolAddress((void**)&pwqt, g_wqt);
    cudaGetSymbolAddress((void**)&pwkt, g_wkt);
    cudaGetSymbolAddress((void**)&pwvt, g_wvt);
    cudaGetSymbolAddress((void**)&pwet, g_wet);

    pe_freq_kernel<<<1, 512>>>();
    transpose_kernel<<<dim3(MLPc/32, Dc/32, NBc), dim3(32,8)>>>(W1, pw1t, Dc, MLPc);
    transpose_kernel<<<dim3(Dc/32, MLPc/32, NBc), dim3(32,8)>>>(W2, pw2t, MLPc, Dc);
    transpose_kernel<<<dim3(2, 2, NBc*Hc), dim3(32,8)>>>(Wq, pwqt, DHc, DHc);
    transpose_kernel<<<dim3(2, 2, NBc*Hc), dim3(32,8)>>>(Wk, pwkt, DHc, DHc);
    transpose_kernel<<<dim3(2, 2, NBc*Hc), dim3(32,8)>>>(Wv, pwvt, DHc, DHc);
    transpose_kernel<<<dim3(Dc/32, Fc/32, 1), dim3(32,8)>>>(embW, pwet, Fc, Dc);
    embed_cls_kernel<<<Bc, 128>>>(cls);
    embed_tc_kernel<<<dim3(Dc/128, BTc/128), 128>>>(src, pwet, embb);
    for (int i = 0; i < NBc; i++) {
        size_t wo = (size_t)i*Hc*DHc*DHc, bo = (size_t)i*Hc*DHc;
        ln_kernel<<<BTc/4, 128>>>(ln1g + i*Dc, ln1b + i*Dc);
        qkv_tc_kernel<<<dim3(Tc/64, Bc*Hc, 3), 128>>>(
            pwqt + wo, bq + bo, pwkt + wo, bk + bo, pwvt + wo, bv + bo);
        attn_tc_kernel<<<dim3(Tc/64, Bc*Hc), 128>>>();
        ln_kernel<<<BTc/4, 128>>>(ln2g + i*Dc, ln2b + i*Dc);
        tc_gemm<0><<<dim3(MLPc/128, BTc/128), 128>>>(
            ph, pw1t + (size_t)i*MLPc*Dc, b1 + (size_t)i*MLPc, pm1, MLPc, Dc);
        tc_gemm<1><<<dim3(Dc/128, BTc/128), 128>>>(
            pm1, pw2t + (size_t)i*Dc*MLPc, b2 + (size_t)i*Dc, px, Dc, MLPc);
    }
    head_kernel<<<1, 512>>>(hW, hb, out);
}